// round 1
// baseline (speedup 1.0000x reference)
#include <cuda_runtime.h>
#include <cuda_bf16.h>
#include <math.h>

// Problem constants
#define BB 16
#define NN 243
#define JJ 17
#define CC 512
#define HH 8
#define DD 64
#define MROWS (BB * NN * JJ)      // 66096
#define BNF   (BB * NN)           // 3888

// Scratch (device globals: allocation-free per harness rules)
__device__ float g_qkv[(size_t)MROWS * 1536];  // (M, 3C)
__device__ float g_att[(size_t)MROWS * CC];    // attention output (M, C)
__device__ float g_y[(size_t)MROWS * CC];      // pre-LN y = x + proj

// ---------------------------------------------------------------------------
// SGEMM: C = A(MxK) @ B(KxN) + bias[N] (+ resid(MxN) optional)
// Block tile 128x128, BK=8, 256 threads, 8x8 per-thread microtile.
// N must be a multiple of 128, K a multiple of 8. M ragged (bounds-checked).
// ---------------------------------------------------------------------------
__global__ __launch_bounds__(256, 2)
void sgemm_kernel(const float* __restrict__ A, const float* __restrict__ Bm,
                  const float* __restrict__ bias, const float* __restrict__ resid,
                  float* __restrict__ Cm, int M, int N, int K) {
    __shared__ __align__(16) float As[8][128];
    __shared__ __align__(16) float Bs[8][128];

    const int tid = threadIdx.x;
    const int bm = blockIdx.y << 7;
    const int bn = blockIdx.x << 7;

    const int arow = tid >> 1;           // 0..127
    const int acol = (tid & 1) << 2;     // 0 or 4
    const int bkk  = tid >> 5;           // 0..7
    const int bcol = (tid & 31) << 2;    // 0..124
    const int ty = tid >> 4;             // 0..15
    const int tx = tid & 15;             // 0..15

    const bool aValid = (bm + arow) < M;
    const float* aPtr = A + (size_t)(bm + arow) * K + acol;
    const float* bPtr = Bm + (size_t)bkk * N + (bn + bcol);

    float4 aR = make_float4(0.f, 0.f, 0.f, 0.f);
    float4 bR;
    if (aValid) aR = *reinterpret_cast<const float4*>(aPtr);
    bR = *reinterpret_cast<const float4*>(bPtr);

    float acc[8][8];
#pragma unroll
    for (int i = 0; i < 8; i++)
#pragma unroll
        for (int j = 0; j < 8; j++) acc[i][j] = 0.f;

    for (int k0 = 0; k0 < K; k0 += 8) {
        As[acol + 0][arow] = aR.x;
        As[acol + 1][arow] = aR.y;
        As[acol + 2][arow] = aR.z;
        As[acol + 3][arow] = aR.w;
        *reinterpret_cast<float4*>(&Bs[bkk][bcol]) = bR;
        __syncthreads();

        if (k0 + 8 < K) {  // prefetch next tile into registers
            if (aValid) aR = *reinterpret_cast<const float4*>(aPtr + k0 + 8);
            bR = *reinterpret_cast<const float4*>(bPtr + (size_t)(k0 + 8) * N);
        }

#pragma unroll
        for (int kk = 0; kk < 8; kk++) {
            float a[8], b[8];
            *reinterpret_cast<float4*>(a)     = *reinterpret_cast<const float4*>(&As[kk][ty << 3]);
            *reinterpret_cast<float4*>(a + 4) = *reinterpret_cast<const float4*>(&As[kk][(ty << 3) + 4]);
            *reinterpret_cast<float4*>(b)     = *reinterpret_cast<const float4*>(&Bs[kk][tx << 3]);
            *reinterpret_cast<float4*>(b + 4) = *reinterpret_cast<const float4*>(&Bs[kk][(tx << 3) + 4]);
#pragma unroll
            for (int i = 0; i < 8; i++)
#pragma unroll
                for (int j = 0; j < 8; j++)
                    acc[i][j] += a[i] * b[j];
        }
        __syncthreads();
    }

    // Epilogue: bias + optional residual
#pragma unroll
    for (int i = 0; i < 8; i++) {
        int row = bm + (ty << 3) + i;
        if (row >= M) continue;
        float* cp = Cm + (size_t)row * N + bn + (tx << 3);
        const float* rp = resid ? (resid + (size_t)row * N + bn + (tx << 3)) : nullptr;
#pragma unroll
        for (int j4 = 0; j4 < 8; j4 += 4) {
            int col = bn + (tx << 3) + j4;
            float4 o;
            o.x = acc[i][j4 + 0] + bias[col + 0];
            o.y = acc[i][j4 + 1] + bias[col + 1];
            o.z = acc[i][j4 + 2] + bias[col + 2];
            o.w = acc[i][j4 + 3] + bias[col + 3];
            if (rp) {
                o.x += rp[j4 + 0];
                o.y += rp[j4 + 1];
                o.z += rp[j4 + 2];
                o.w += rp[j4 + 3];
            }
            *reinterpret_cast<float4*>(cp + j4) = o;
        }
    }
}

// ---------------------------------------------------------------------------
// Attention per (frame, head): 17x17 scores, softmax, 13 triplet updates, P@V
// One block of 64 threads per (bn, h). qkv row layout: [3][H][D] per token.
// ---------------------------------------------------------------------------
__global__ __launch_bounds__(64)
void attn_kernel(const float* __restrict__ qkv, float* __restrict__ out) {
    const int bh = blockIdx.x;
    const int bn = bh >> 3;
    const int h  = bh & 7;
    const int d  = threadIdx.x;   // 0..63

    __shared__ float qs[17][64];
    __shared__ float ks[17][64];
    __shared__ float vs[17][64];
    __shared__ float S[17][17];

    const float* base = qkv + (size_t)bn * 17 * 1536 + h * 64;
#pragma unroll
    for (int j = 0; j < 17; j++) {
        const float* r = base + (size_t)j * 1536;
        qs[j][d] = r[d];
        ks[j][d] = r[512 + d];
        vs[j][d] = r[1024 + d];
    }
    __syncthreads();

    // scores
    for (int idx = d; idx < 289; idx += 64) {
        int i = idx / 17;
        int j = idx - i * 17;
        float s = 0.f;
#pragma unroll
        for (int dd = 0; dd < 64; dd++) s += qs[i][dd] * ks[j][dd];
        S[i][j] = s * 0.125f;   // 1/sqrt(64)
    }
    __syncthreads();

    // softmax per row
    if (d < 17) {
        float mx = -1e30f;
#pragma unroll
        for (int j = 0; j < 17; j++) mx = fmaxf(mx, S[d][j]);
        float sum = 0.f;
#pragma unroll
        for (int j = 0; j < 17; j++) {
            float e = expf(S[d][j] - mx);
            S[d][j] = e;
            sum += e;
        }
        float inv = 1.f / sum;
#pragma unroll
        for (int j = 0; j < 17; j++) S[d][j] *= inv;
    }
    __syncthreads();

    // sequential skeleton triplet adjustments (order matters)
    if (d == 0) {
        const int trip[13][3] = {
            {0,1,2},{1,2,3},{0,4,5},{4,5,6},{0,7,8},{7,8,9},{8,9,10},
            {7,8,11},{8,11,12},{11,12,13},{7,8,14},{8,14,15},{14,15,16}};
#pragma unroll
        for (int t = 0; t < 13; t++) {
            int jp = trip[t][0], j = trip[t][1], jc = trip[t][2];
            float half = S[j][jp] * 0.5f;
            S[j][jc] += half;
            S[jc][j] += half;
        }
    }
    __syncthreads();

    // out[i,:] = P @ V ; write as (token, h*64+d)
#pragma unroll
    for (int i = 0; i < 17; i++) {
        float o = 0.f;
#pragma unroll
        for (int j = 0; j < 17; j++) o += S[i][j] * vs[j][d];
        out[((size_t)(bn * 17 + i)) * 512 + h * 64 + d] = o;
    }
}

// ---------------------------------------------------------------------------
// LayerNorm (no affine) over last dim 512. One block (128 threads) per row.
// ---------------------------------------------------------------------------
__global__ __launch_bounds__(128)
void ln_kernel(const float* __restrict__ Y, float* __restrict__ O) {
    const int row = blockIdx.x;
    const int t = threadIdx.x;
    const float4* yp = reinterpret_cast<const float4*>(Y + (size_t)row * 512);
    float4* op = reinterpret_cast<float4*>(O + (size_t)row * 512);

    float4 v = yp[t];
    float s = v.x + v.y + v.z + v.w;
    float q = v.x * v.x + v.y * v.y + v.z * v.z + v.w * v.w;
#pragma unroll
    for (int o = 16; o > 0; o >>= 1) {
        s += __shfl_xor_sync(0xffffffffu, s, o);
        q += __shfl_xor_sync(0xffffffffu, q, o);
    }
    __shared__ float ss[4], sq[4];
    int w = t >> 5;
    if ((t & 31) == 0) { ss[w] = s; sq[w] = q; }
    __syncthreads();
    s = ss[0] + ss[1] + ss[2] + ss[3];
    q = sq[0] + sq[1] + sq[2] + sq[3];

    const float inv512 = 1.f / 512.f;
    float mean = s * inv512;
    float var = q * inv512 - mean * mean;
    float r = rsqrtf(var + 1e-5f);

    float4 o4;
    o4.x = (v.x - mean) * r;
    o4.y = (v.y - mean) * r;
    o4.z = (v.z - mean) * r;
    o4.w = (v.w - mean) * r;
    op[t] = o4;
}

// ---------------------------------------------------------------------------
extern "C" void kernel_launch(void* const* d_in, const int* in_sizes, int n_in,
                              void* d_out, int out_size) {
    const float* x     = (const float*)d_in[0];
    const float* Wqkv  = (const float*)d_in[1];
    const float* bqkv  = (const float*)d_in[2];
    const float* Wproj = (const float*)d_in[3];
    const float* bproj = (const float*)d_in[4];
    float* out = (float*)d_out;

    float *qkv, *att, *y;
    cudaGetSymbolAddress((void**)&qkv, g_qkv);
    cudaGetSymbolAddress((void**)&att, g_att);
    cudaGetSymbolAddress((void**)&y, g_y);

    dim3 blk(256);
    dim3 g1(1536 / 128, (MROWS + 127) / 128);   // (12, 517)
    sgemm_kernel<<<g1, blk>>>(x, Wqkv, bqkv, nullptr, qkv, MROWS, 1536, 512);

    attn_kernel<<<BNF * HH, 64>>>(qkv, att);

    dim3 g2(512 / 128, (MROWS + 127) / 128);    // (4, 517)
    sgemm_kernel<<<g2, blk>>>(att, Wproj, bproj, x, y, MROWS, 512, 512);

    ln_kernel<<<MROWS, 128>>>(y, out);
}

// round 2
// speedup vs baseline: 1.6476x; 1.6476x over previous
#include <cuda_runtime.h>
#include <cuda_bf16.h>
#include <math.h>
#include <stdint.h>

// Problem constants
#define BB 16
#define NN 243
#define JJ 17
#define CC 512
#define HH 8
#define DD 64
#define MROWS (BB * NN * JJ)      // 66096
#define BNF   (BB * NN)           // 3888

// Scratch (device globals: allocation-free per harness rules)
__device__ float g_qkv[(size_t)MROWS * 1536];  // (M, 3C)
__device__ float g_att[(size_t)MROWS * CC];    // attention output (M, C)
__device__ float g_y[(size_t)MROWS * CC];      // pre-LN y = x + proj

// ---------------------------------------------------------------------------
// Split-bf16 tensor-core GEMM: C = A(MxK) @ B(KxN) + bias[N] (+ resid optional)
// fp32 inputs decomposed on the fly: a = hi(bf16) + lo(bf16); accumulate
// hi*hi + hi*lo + lo*hi in fp32 via mma.sync.m16n8k16 -> ~fp32 accuracy.
// Block tile 128x128, BK=32, 256 threads (8 warps, 2x4), warp tile 64x32.
// N % 128 == 0, K % 32 == 0 required. M ragged (guarded).
// ---------------------------------------------------------------------------
__device__ __forceinline__ void mma16816(float* c, const uint32_t* a, const uint32_t* b) {
    asm volatile(
        "mma.sync.aligned.m16n8k16.row.col.f32.bf16.bf16.f32 "
        "{%0,%1,%2,%3}, {%4,%5,%6,%7}, {%8,%9}, {%0,%1,%2,%3};\n"
        : "+f"(c[0]), "+f"(c[1]), "+f"(c[2]), "+f"(c[3])
        : "r"(a[0]), "r"(a[1]), "r"(a[2]), "r"(a[3]), "r"(b[0]), "r"(b[1]));
}

__device__ __forceinline__ uint32_t bpack(__nv_bfloat16 x, __nv_bfloat16 y) {
    __nv_bfloat162 v = __halves2bfloat162(x, y);   // x in low 16 bits
    return *reinterpret_cast<uint32_t*>(&v);
}

__global__ __launch_bounds__(256)
void hgemm_kernel(const float* __restrict__ A, const float* __restrict__ Bm,
                  const float* __restrict__ bias, const float* __restrict__ resid,
                  float* __restrict__ Cm, int M, int N, int K) {
    // A tiles: [m=128][k=32] padded to 40 bf16/row (conflict-free frag loads)
    __shared__ __align__(16) __nv_bfloat16 Ah[128][40];
    __shared__ __align__(16) __nv_bfloat16 Al[128][40];
    // B tiles: k-major [k=32][n=128] padded to 132
    __shared__ __align__(16) __nv_bfloat16 Bh[32][132];
    __shared__ __align__(16) __nv_bfloat16 Bl[32][132];

    const int tid = threadIdx.x;
    const int bm = blockIdx.y << 7;
    const int bn = blockIdx.x << 7;
    const int w = tid >> 5, lane = tid & 31;
    const int wm = w & 1;         // warp row (0..1) -> 64 rows
    const int wn = w >> 1;        // warp col (0..3) -> 32 cols
    const int g = lane >> 2;      // group id (0..7)
    const int t = lane & 3;       // thread-in-group (0..3)

    float acc[4][4][4];
#pragma unroll
    for (int i = 0; i < 4; i++)
#pragma unroll
        for (int j = 0; j < 4; j++)
#pragma unroll
            for (int e = 0; e < 4; e++) acc[i][j][e] = 0.f;

    // Global staging assignment
    const int ar = tid >> 1;               // A row (0..127)
    const int ac = (tid & 1) << 4;         // A col base (0 or 16)
    const bool aOk = (bm + ar) < M;
    const float* aG = A + (size_t)(bm + ar) * K + ac;
    const int bkr = tid >> 5;              // B k row base (pass p: k = p*8 + bkr)
    const int bnc = (lane) << 2;           // B n col (0..124)
    const float* bG = Bm + (size_t)bkr * N + bn + bnc;

    float4 aS[4], bS[4];

    // prologue: stage tile k0=0
    if (aOk) {
#pragma unroll
        for (int q = 0; q < 4; q++) aS[q] = *(const float4*)(aG + q * 4);
    } else {
#pragma unroll
        for (int q = 0; q < 4; q++) aS[q] = make_float4(0.f, 0.f, 0.f, 0.f);
    }
#pragma unroll
    for (int p = 0; p < 4; p++) bS[p] = *(const float4*)(bG + (size_t)(p * 8) * N);

    const int T = K >> 5;
    for (int kt = 0; kt < T; kt++) {
        // ---- store staged tile into smem as bf16 hi/lo ----
#pragma unroll
        for (int q = 0; q < 4; q++) {
            float vv[4] = {aS[q].x, aS[q].y, aS[q].z, aS[q].w};
#pragma unroll
            for (int e = 0; e < 4; e++) {
                __nv_bfloat16 h = __float2bfloat16(vv[e]);
                Ah[ar][ac + q * 4 + e] = h;
                Al[ar][ac + q * 4 + e] = __float2bfloat16(vv[e] - __bfloat162float(h));
            }
        }
#pragma unroll
        for (int p = 0; p < 4; p++) {
            int k = p * 8 + bkr;
            float vv[4] = {bS[p].x, bS[p].y, bS[p].z, bS[p].w};
#pragma unroll
            for (int e = 0; e < 4; e++) {
                __nv_bfloat16 h = __float2bfloat16(vv[e]);
                Bh[k][bnc + e] = h;
                Bl[k][bnc + e] = __float2bfloat16(vv[e] - __bfloat162float(h));
            }
        }
        __syncthreads();

        // ---- prefetch next tile into registers ----
        if (kt + 1 < T) {
            int k0 = (kt + 1) << 5;
            if (aOk) {
#pragma unroll
                for (int q = 0; q < 4; q++) aS[q] = *(const float4*)(aG + k0 + q * 4);
            }
#pragma unroll
            for (int p = 0; p < 4; p++) bS[p] = *(const float4*)(bG + (size_t)(k0 + p * 8) * N);
        }

        // ---- compute: 2 k-chunks of 16, 3 split products each ----
#pragma unroll
        for (int kc = 0; kc < 2; kc++) {
            uint32_t ahf[4][4], alf[4][4], bhf[4][2], blf[4][2];
            const int c0 = kc * 16 + t * 2;
#pragma unroll
            for (int mi = 0; mi < 4; mi++) {
                int r0 = wm * 64 + mi * 16 + g;
                ahf[mi][0] = *(const uint32_t*)&Ah[r0][c0];
                ahf[mi][1] = *(const uint32_t*)&Ah[r0 + 8][c0];
                ahf[mi][2] = *(const uint32_t*)&Ah[r0][c0 + 8];
                ahf[mi][3] = *(const uint32_t*)&Ah[r0 + 8][c0 + 8];
                alf[mi][0] = *(const uint32_t*)&Al[r0][c0];
                alf[mi][1] = *(const uint32_t*)&Al[r0 + 8][c0];
                alf[mi][2] = *(const uint32_t*)&Al[r0][c0 + 8];
                alf[mi][3] = *(const uint32_t*)&Al[r0 + 8][c0 + 8];
            }
#pragma unroll
            for (int ni = 0; ni < 4; ni++) {
                int nn = wn * 32 + ni * 8 + g;
                bhf[ni][0] = bpack(Bh[c0][nn], Bh[c0 + 1][nn]);
                bhf[ni][1] = bpack(Bh[c0 + 8][nn], Bh[c0 + 9][nn]);
                blf[ni][0] = bpack(Bl[c0][nn], Bl[c0 + 1][nn]);
                blf[ni][1] = bpack(Bl[c0 + 8][nn], Bl[c0 + 9][nn]);
            }
#pragma unroll
            for (int mi = 0; mi < 4; mi++)
#pragma unroll
                for (int ni = 0; ni < 4; ni++) {
                    mma16816(acc[mi][ni], ahf[mi], bhf[ni]);
                    mma16816(acc[mi][ni], ahf[mi], blf[ni]);
                    mma16816(acc[mi][ni], alf[mi], bhf[ni]);
                }
        }
        __syncthreads();
    }

    // ---- epilogue: bias (+resid), fp32 store ----
#pragma unroll
    for (int mi = 0; mi < 4; mi++) {
#pragma unroll
        for (int ni = 0; ni < 4; ni++) {
            int col = bn + wn * 32 + ni * 8 + t * 2;
            float bb0 = bias[col], bb1 = bias[col + 1];
            int r0 = bm + wm * 64 + mi * 16 + g;
            if (r0 < M) {
                float2 o;
                o.x = acc[mi][ni][0] + bb0;
                o.y = acc[mi][ni][1] + bb1;
                if (resid) {
                    const float2 rr = *(const float2*)(resid + (size_t)r0 * N + col);
                    o.x += rr.x; o.y += rr.y;
                }
                *(float2*)(Cm + (size_t)r0 * N + col) = o;
            }
            int r1 = r0 + 8;
            if (r1 < M) {
                float2 o;
                o.x = acc[mi][ni][2] + bb0;
                o.y = acc[mi][ni][3] + bb1;
                if (resid) {
                    const float2 rr = *(const float2*)(resid + (size_t)r1 * N + col);
                    o.x += rr.x; o.y += rr.y;
                }
                *(float2*)(Cm + (size_t)r1 * N + col) = o;
            }
        }
    }
}

// ---------------------------------------------------------------------------
// Attention per (frame, head): 17x17 scores, softmax, 13 triplet updates, P@V
// ---------------------------------------------------------------------------
__global__ __launch_bounds__(64)
void attn_kernel(const float* __restrict__ qkv, float* __restrict__ out) {
    const int bh = blockIdx.x;
    const int bn = bh >> 3;
    const int h  = bh & 7;
    const int d  = threadIdx.x;   // 0..63

    __shared__ float qs[17][64];
    __shared__ float ks[17][64];
    __shared__ float vs[17][64];
    __shared__ float S[17][17];

    const float* base = qkv + (size_t)bn * 17 * 1536 + h * 64;
#pragma unroll
    for (int j = 0; j < 17; j++) {
        const float* r = base + (size_t)j * 1536;
        qs[j][d] = r[d];
        ks[j][d] = r[512 + d];
        vs[j][d] = r[1024 + d];
    }
    __syncthreads();

    for (int idx = d; idx < 289; idx += 64) {
        int i = idx / 17;
        int j = idx - i * 17;
        float s = 0.f;
#pragma unroll
        for (int dd = 0; dd < 64; dd++) s += qs[i][dd] * ks[j][dd];
        S[i][j] = s * 0.125f;
    }
    __syncthreads();

    if (d < 17) {
        float mx = -1e30f;
#pragma unroll
        for (int j = 0; j < 17; j++) mx = fmaxf(mx, S[d][j]);
        float sum = 0.f;
#pragma unroll
        for (int j = 0; j < 17; j++) {
            float e = expf(S[d][j] - mx);
            S[d][j] = e;
            sum += e;
        }
        float inv = 1.f / sum;
#pragma unroll
        for (int j = 0; j < 17; j++) S[d][j] *= inv;
    }
    __syncthreads();

    if (d == 0) {
        const int trip[13][3] = {
            {0,1,2},{1,2,3},{0,4,5},{4,5,6},{0,7,8},{7,8,9},{8,9,10},
            {7,8,11},{8,11,12},{11,12,13},{7,8,14},{8,14,15},{14,15,16}};
#pragma unroll
        for (int tt = 0; tt < 13; tt++) {
            int jp = trip[tt][0], j = trip[tt][1], jc = trip[tt][2];
            float half = S[j][jp] * 0.5f;
            S[j][jc] += half;
            S[jc][j] += half;
        }
    }
    __syncthreads();

#pragma unroll
    for (int i = 0; i < 17; i++) {
        float o = 0.f;
#pragma unroll
        for (int j = 0; j < 17; j++) o += S[i][j] * vs[j][d];
        out[((size_t)(bn * 17 + i)) * 512 + h * 64 + d] = o;
    }
}

// ---------------------------------------------------------------------------
// LayerNorm (no affine) over last dim 512. One block (128 threads) per row.
// ---------------------------------------------------------------------------
__global__ __launch_bounds__(128)
void ln_kernel(const float* __restrict__ Y, float* __restrict__ O) {
    const int row = blockIdx.x;
    const int t = threadIdx.x;
    const float4* yp = reinterpret_cast<const float4*>(Y + (size_t)row * 512);
    float4* op = reinterpret_cast<float4*>(O + (size_t)row * 512);

    float4 v = yp[t];
    float s = v.x + v.y + v.z + v.w;
    float q = v.x * v.x + v.y * v.y + v.z * v.z + v.w * v.w;
#pragma unroll
    for (int o = 16; o > 0; o >>= 1) {
        s += __shfl_xor_sync(0xffffffffu, s, o);
        q += __shfl_xor_sync(0xffffffffu, q, o);
    }
    __shared__ float ss[4], sq[4];
    int w = t >> 5;
    if ((t & 31) == 0) { ss[w] = s; sq[w] = q; }
    __syncthreads();
    s = ss[0] + ss[1] + ss[2] + ss[3];
    q = sq[0] + sq[1] + sq[2] + sq[3];

    const float inv512 = 1.f / 512.f;
    float mean = s * inv512;
    float var = q * inv512 - mean * mean;
    float r = rsqrtf(var + 1e-5f);

    float4 o4;
    o4.x = (v.x - mean) * r;
    o4.y = (v.y - mean) * r;
    o4.z = (v.z - mean) * r;
    o4.w = (v.w - mean) * r;
    op[t] = o4;
}

// ---------------------------------------------------------------------------
extern "C" void kernel_launch(void* const* d_in, const int* in_sizes, int n_in,
                              void* d_out, int out_size) {
    const float* x     = (const float*)d_in[0];
    const float* Wqkv  = (const float*)d_in[1];
    const float* bqkv  = (const float*)d_in[2];
    const float* Wproj = (const float*)d_in[3];
    const float* bproj = (const float*)d_in[4];
    float* out = (float*)d_out;

    float *qkv, *att, *y;
    cudaGetSymbolAddress((void**)&qkv, g_qkv);
    cudaGetSymbolAddress((void**)&att, g_att);
    cudaGetSymbolAddress((void**)&y, g_y);

    dim3 blk(256);
    dim3 g1(1536 / 128, (MROWS + 127) / 128);   // (12, 517)
    hgemm_kernel<<<g1, blk>>>(x, Wqkv, bqkv, nullptr, qkv, MROWS, 1536, 512);

    attn_kernel<<<BNF * HH, 64>>>(qkv, att);

    dim3 g2(512 / 128, (MROWS + 127) / 128);    // (4, 517)
    hgemm_kernel<<<g2, blk>>>(att, Wproj, bproj, x, y, MROWS, 512, 512);

    ln_kernel<<<MROWS, 128>>>(y, out);
}

// round 4
// speedup vs baseline: 1.7183x; 1.0429x over previous
#include <cuda_runtime.h>
#include <cuda_bf16.h>
#include <math.h>
#include <stdint.h>

// Problem constants
#define BB 16
#define NN 243
#define JJ 17
#define CC 512
#define HH 8
#define MROWS (BB * NN * JJ)      // 66096
#define BNF   (BB * NN)           // 3888
#define KDIM  512

// Scratch (device globals: allocation-free per harness rules)
__device__ float g_qkv[(size_t)MROWS * 1536];
__device__ float g_y[(size_t)MROWS * CC];
__device__ __nv_bfloat16 g_xh[(size_t)MROWS * CC];
__device__ __nv_bfloat16 g_xl[(size_t)MROWS * CC];
__device__ __nv_bfloat16 g_ah[(size_t)MROWS * CC];
__device__ __nv_bfloat16 g_al[(size_t)MROWS * CC];
__device__ __nv_bfloat16 g_w1h[1536 * 512];   // Wqkv^T split, [N][K]
__device__ __nv_bfloat16 g_w1l[1536 * 512];
__device__ __nv_bfloat16 g_w2h[512 * 512];    // Wproj^T split
__device__ __nv_bfloat16 g_w2l[512 * 512];

// ---------------------------------------------------------------------------
// PTX helpers
// ---------------------------------------------------------------------------
__device__ __forceinline__ uint32_t smem_u32(const void* p) {
    uint32_t a;
    asm("{ .reg .u64 t; cvta.to.shared.u64 t, %1; cvt.u32.u64 %0, t; }"
        : "=r"(a) : "l"(p));
    return a;
}

#define CP_ASYNC16(dst, src, sz) \
    asm volatile("cp.async.cg.shared.global [%0], [%1], 16, %2;\n" \
                 :: "r"((uint32_t)(dst)), "l"(src), "r"(sz))
#define CP_COMMIT() asm volatile("cp.async.commit_group;\n" ::: "memory")
#define CP_WAIT1()  asm volatile("cp.async.wait_group 1;\n" ::: "memory")

#define LDSM4(r0, r1, r2, r3, a) \
    asm volatile("ldmatrix.sync.aligned.m8n8.x4.shared.b16 {%0,%1,%2,%3}, [%4];" \
                 : "=r"(r0), "=r"(r1), "=r"(r2), "=r"(r3) : "r"(a))

__device__ __forceinline__ void mma16816(float* c, const uint32_t* a, const uint32_t* b) {
    asm volatile(
        "mma.sync.aligned.m16n8k16.row.col.f32.bf16.bf16.f32 "
        "{%0,%1,%2,%3}, {%4,%5,%6,%7}, {%8,%9}, {%0,%1,%2,%3};\n"
        : "+f"(c[0]), "+f"(c[1]), "+f"(c[2]), "+f"(c[3])
        : "r"(a[0]), "r"(a[1]), "r"(a[2]), "r"(a[3]), "r"(b[0]), "r"(b[1]));
}

// ---------------------------------------------------------------------------
// Split-bf16 HMMA GEMM: C(MxN) = [Ah+Al](MxK) @ [Bh+Bl]^T(NxK) + bias (+resid)
// BM=128, BN=128, BK=32, 256 threads (8 warps 2x4), warp tile 64x32.
// 3-stage cp.async pipeline; ldmatrix fragment loads from 80B-padded rows.
// K = 512. M ragged (zero-filled loads, guarded stores). N % 128 == 0.
// ---------------------------------------------------------------------------
#define ROWB 80                       // padded row stride in bytes (40 bf16)
#define ST_AH 0
#define ST_AL (128 * ROWB)            // 10240
#define ST_BH (2 * 128 * ROWB)
#define ST_BL (3 * 128 * ROWB)
#define STAGE_BYTES (4 * 128 * ROWB)  // 40960
#define NSTAGE 3
#define GEMM_SMEM (NSTAGE * STAGE_BYTES)  // 122880

__device__ __forceinline__ void load_tile(
    uint32_t stage,
    const __nv_bfloat16* __restrict__ Ah, const __nv_bfloat16* __restrict__ Al,
    const __nv_bfloat16* __restrict__ Bh, const __nv_bfloat16* __restrict__ Bl,
    int bm, int bn, int M, int kt, int tid)
{
    const int k0 = kt * 32;
#pragma unroll
    for (int i = 0; i < 2; i++) {
        int q = i * 256 + tid;            // 0..511
        int row = q >> 2, c = q & 3;      // row 0..127, 16B chunk 0..3
        uint32_t dof = row * ROWB + c * 16;
        size_t ga = (size_t)(bm + row) * KDIM + k0 + c * 8;
        int p = ((bm + row) < M) ? 16 : 0;
        CP_ASYNC16(stage + ST_AH + dof, Ah + ga, p);
        CP_ASYNC16(stage + ST_AL + dof, Al + ga, p);
        size_t gb = (size_t)(bn + row) * KDIM + k0 + c * 8;
        CP_ASYNC16(stage + ST_BH + dof, Bh + gb, 16);
        CP_ASYNC16(stage + ST_BL + dof, Bl + gb, 16);
    }
}

__global__ void __launch_bounds__(256, 1) gemm_mma(
    const __nv_bfloat16* __restrict__ Ah, const __nv_bfloat16* __restrict__ Al,
    const __nv_bfloat16* __restrict__ Bh, const __nv_bfloat16* __restrict__ Bl,
    const float* __restrict__ bias, const float* __restrict__ resid,
    float* __restrict__ Cm, int M, int N)
{
    extern __shared__ char smem[];
    const uint32_t sb = smem_u32(smem);
    const int tid = threadIdx.x;
    const int w = tid >> 5, lane = tid & 31;
    const int wm = w & 1;                 // 2 warp-rows of 64
    const int wn = w >> 1;                // 4 warp-cols of 32
    const int bn = blockIdx.x << 7;
    const int bm = blockIdx.y << 7;

    float acc[4][4][4];
#pragma unroll
    for (int i = 0; i < 4; i++)
#pragma unroll
        for (int j = 0; j < 4; j++)
#pragma unroll
            for (int e = 0; e < 4; e++) acc[i][j][e] = 0.f;

    // ldmatrix per-lane row/col within tile: row = base + (lane&15), k8 = lane>>4
    const int lrow = lane & 15;
    const int lkb = (lane >> 4) << 4;     // byte offset of k8 half (8 bf16 = 16B)
    const uint32_t a_lane_off = (wm * 64 + lrow) * ROWB + lkb;
    const uint32_t b_lane_off = (wn * 32 + lrow) * ROWB + lkb;

    const int T = KDIM / 32;              // 16
    load_tile(sb, Ah, Al, Bh, Bl, bm, bn, M, 0, tid);
    CP_COMMIT();
    load_tile(sb + STAGE_BYTES, Ah, Al, Bh, Bl, bm, bn, M, 1, tid);
    CP_COMMIT();

    int sidx = 0;
    for (int kt = 0; kt < T; kt++) {
        CP_WAIT1();                        // stage kt ready
        __syncthreads();                   // all warps done with stage being reloaded

        if (kt + 2 < T)
            load_tile(sb + ((sidx + 2 >= NSTAGE) ? sidx + 2 - NSTAGE : sidx + 2) * STAGE_BYTES,
                      Ah, Al, Bh, Bl, bm, bn, M, kt + 2, tid);
        CP_COMMIT();

        const uint32_t stage = sb + sidx * STAGE_BYTES;
#pragma unroll
        for (int kc = 0; kc < 2; kc++) {
            const uint32_t kbo = kc * 32;  // 16 bf16 = 32B per k-chunk
            uint32_t ah[4][4], al[4][4], bh[4][2], bl[4][2];
#pragma unroll
            for (int mi = 0; mi < 4; mi++) {
                uint32_t ad = stage + a_lane_off + mi * (16 * ROWB) + kbo;
                LDSM4(ah[mi][0], ah[mi][1], ah[mi][2], ah[mi][3], ad + ST_AH);
                LDSM4(al[mi][0], al[mi][1], al[mi][2], al[mi][3], ad + ST_AL);
            }
#pragma unroll
            for (int nj = 0; nj < 2; nj++) {   // each x4 covers two n8 tiles
                uint32_t bd = stage + b_lane_off + nj * (16 * ROWB) + kbo;
                uint32_t h0, h1, h2, h3, l0, l1, l2, l3;
                LDSM4(h0, h1, h2, h3, bd + ST_BH);
                LDSM4(l0, l1, l2, l3, bd + ST_BL);
                bh[nj * 2 + 0][0] = h0; bh[nj * 2 + 0][1] = h2;
                bh[nj * 2 + 1][0] = h1; bh[nj * 2 + 1][1] = h3;
                bl[nj * 2 + 0][0] = l0; bl[nj * 2 + 0][1] = l2;
                bl[nj * 2 + 1][0] = l1; bl[nj * 2 + 1][1] = l3;
            }
#pragma unroll
            for (int mi = 0; mi < 4; mi++)
#pragma unroll
                for (int ni = 0; ni < 4; ni++) {
                    mma16816(acc[mi][ni], ah[mi], bh[ni]);
                    mma16816(acc[mi][ni], ah[mi], bl[ni]);
                    mma16816(acc[mi][ni], al[mi], bh[ni]);
                }
        }
        sidx = (sidx + 1 >= NSTAGE) ? 0 : sidx + 1;
    }

    // Epilogue: c-frag mapping: thread g*4+t holds (m=g, n=2t), (m=g+8, n=2t)
    const int g = lane >> 2, t = lane & 3;
#pragma unroll
    for (int mi = 0; mi < 4; mi++) {
#pragma unroll
        for (int ni = 0; ni < 4; ni++) {
            int col = bn + wn * 32 + ni * 8 + t * 2;
            float bb0 = bias[col], bb1 = bias[col + 1];
            int r0 = bm + wm * 64 + mi * 16 + g;
            if (r0 < M) {
                float2 o;
                o.x = acc[mi][ni][0] + bb0;
                o.y = acc[mi][ni][1] + bb1;
                if (resid) {
                    const float2 rr = *(const float2*)(resid + (size_t)r0 * N + col);
                    o.x += rr.x; o.y += rr.y;
                }
                *(float2*)(Cm + (size_t)r0 * N + col) = o;
            }
            int r1 = r0 + 8;
            if (r1 < M) {
                float2 o;
                o.x = acc[mi][ni][2] + bb0;
                o.y = acc[mi][ni][3] + bb1;
                if (resid) {
                    const float2 rr = *(const float2*)(resid + (size_t)r1 * N + col);
                    o.x += rr.x; o.y += rr.y;
                }
                *(float2*)(Cm + (size_t)r1 * N + col) = o;
            }
        }
    }
}

// ---------------------------------------------------------------------------
// Elementwise fp32 -> bf16 hi/lo split
// ---------------------------------------------------------------------------
__global__ void split_kernel(const float* __restrict__ src,
                             __nv_bfloat16* __restrict__ hi,
                             __nv_bfloat16* __restrict__ lo, int n4) {
    int i = blockIdx.x * blockDim.x + threadIdx.x;
    if (i >= n4) return;
    float4 v = ((const float4*)src)[i];
    __nv_bfloat16 h0 = __float2bfloat16(v.x), h1 = __float2bfloat16(v.y);
    __nv_bfloat16 h2 = __float2bfloat16(v.z), h3 = __float2bfloat16(v.w);
    __nv_bfloat162* hp = (__nv_bfloat162*)hi;
    __nv_bfloat162* lp = (__nv_bfloat162*)lo;
    hp[2 * i]     = __halves2bfloat162(h0, h1);
    hp[2 * i + 1] = __halves2bfloat162(h2, h3);
    lp[2 * i]     = __halves2bfloat162(__float2bfloat16(v.x - __bfloat162float(h0)),
                                       __float2bfloat16(v.y - __bfloat162float(h1)));
    lp[2 * i + 1] = __halves2bfloat162(__float2bfloat16(v.z - __bfloat162float(h2)),
                                       __float2bfloat16(v.w - __bfloat162float(h3)));
}

// Transpose + split: W (KxN row-major) -> hiT/loT (NxK row-major)
__global__ void wsplit_kernel(const float* __restrict__ W,
                              __nv_bfloat16* __restrict__ hiT,
                              __nv_bfloat16* __restrict__ loT, int K, int N) {
    __shared__ float t[32][33];
    const int n0 = blockIdx.x * 32, k0 = blockIdx.y * 32;
    const int tx = threadIdx.x, ty = threadIdx.y;
    for (int r = ty; r < 32; r += 8)
        t[r][tx] = W[(size_t)(k0 + r) * N + n0 + tx];
    __syncthreads();
    for (int r = ty; r < 32; r += 8) {
        float v = t[tx][r];                       // (k0+tx, n0+r)
        __nv_bfloat16 h = __float2bfloat16(v);
        size_t o = (size_t)(n0 + r) * K + k0 + tx;
        hiT[o] = h;
        loT[o] = __float2bfloat16(v - __bfloat162float(h));
    }
}

// ---------------------------------------------------------------------------
// Attention per (frame, head): 17x17, softmax, 13 triplets, P@V. Output split.
// ---------------------------------------------------------------------------
__global__ __launch_bounds__(64)
void attn_kernel(const float* __restrict__ qkv,
                 __nv_bfloat16* __restrict__ oh, __nv_bfloat16* __restrict__ ol) {
    const int bh = blockIdx.x;
    const int bn = bh >> 3;
    const int h  = bh & 7;
    const int d  = threadIdx.x;

    __shared__ float qs[17][64];
    __shared__ float ks[17][64];
    __shared__ float vs[17][64];
    __shared__ float S[17][17];

    const float* base = qkv + (size_t)bn * 17 * 1536 + h * 64;
#pragma unroll
    for (int j = 0; j < 17; j++) {
        const float* r = base + (size_t)j * 1536;
        qs[j][d] = r[d];
        ks[j][d] = r[512 + d];
        vs[j][d] = r[1024 + d];
    }
    __syncthreads();

    for (int idx = d; idx < 289; idx += 64) {
        int i = idx / 17;
        int j = idx - i * 17;
        float s = 0.f;
#pragma unroll
        for (int dd = 0; dd < 64; dd++) s += qs[i][dd] * ks[j][dd];
        S[i][j] = s * 0.125f;
    }
    __syncthreads();

    if (d < 17) {
        float mx = -1e30f;
#pragma unroll
        for (int j = 0; j < 17; j++) mx = fmaxf(mx, S[d][j]);
        float sum = 0.f;
#pragma unroll
        for (int j = 0; j < 17; j++) {
            float e = expf(S[d][j] - mx);
            S[d][j] = e;
            sum += e;
        }
        float inv = 1.f / sum;
#pragma unroll
        for (int j = 0; j < 17; j++) S[d][j] *= inv;
    }
    __syncthreads();

    if (d == 0) {
        const int trip[13][3] = {
            {0,1,2},{1,2,3},{0,4,5},{4,5,6},{0,7,8},{7,8,9},{8,9,10},
            {7,8,11},{8,11,12},{11,12,13},{7,8,14},{8,14,15},{14,15,16}};
#pragma unroll
        for (int tt = 0; tt < 13; tt++) {
            int jp = trip[tt][0], j = trip[tt][1], jc = trip[tt][2];
            float half = S[j][jp] * 0.5f;
            S[j][jc] += half;
            S[jc][j] += half;
        }
    }
    __syncthreads();

#pragma unroll
    for (int i = 0; i < 17; i++) {
        float o = 0.f;
#pragma unroll
        for (int j = 0; j < 17; j++) o += S[i][j] * vs[j][d];
        size_t idx = ((size_t)(bn * 17 + i)) * 512 + h * 64 + d;
        __nv_bfloat16 hh = __float2bfloat16(o);
        oh[idx] = hh;
        ol[idx] = __float2bfloat16(o - __bfloat162float(hh));
    }
}

// ---------------------------------------------------------------------------
// LayerNorm (no affine) over last dim 512
// ---------------------------------------------------------------------------
__global__ __launch_bounds__(128)
void ln_kernel(const float* __restrict__ Y, float* __restrict__ O) {
    const int row = blockIdx.x;
    const int t = threadIdx.x;
    const float4* yp = reinterpret_cast<const float4*>(Y + (size_t)row * 512);
    float4* op = reinterpret_cast<float4*>(O + (size_t)row * 512);

    float4 v = yp[t];
    float s = v.x + v.y + v.z + v.w;
    float q = v.x * v.x + v.y * v.y + v.z * v.z + v.w * v.w;
#pragma unroll
    for (int o = 16; o > 0; o >>= 1) {
        s += __shfl_xor_sync(0xffffffffu, s, o);
        q += __shfl_xor_sync(0xffffffffu, q, o);
    }
    __shared__ float ss[4], sq[4];
    int w = t >> 5;
    if ((t & 31) == 0) { ss[w] = s; sq[w] = q; }
    __syncthreads();
    s = ss[0] + ss[1] + ss[2] + ss[3];
    q = sq[0] + sq[1] + sq[2] + sq[3];

    const float inv512 = 1.f / 512.f;
    float mean = s * inv512;
    float var = q * inv512 - mean * mean;
    float r = rsqrtf(var + 1e-5f);

    float4 o4;
    o4.x = (v.x - mean) * r;
    o4.y = (v.y - mean) * r;
    o4.z = (v.z - mean) * r;
    o4.w = (v.w - mean) * r;
    op[t] = o4;
}

// ---------------------------------------------------------------------------
extern "C" void kernel_launch(void* const* d_in, const int* in_sizes, int n_in,
                              void* d_out, int out_size) {
    const float* x     = (const float*)d_in[0];
    const float* Wqkv  = (const float*)d_in[1];
    const float* bqkv  = (const float*)d_in[2];
    const float* Wproj = (const float*)d_in[3];
    const float* bproj = (const float*)d_in[4];
    float* out = (float*)d_out;

    float *qkv, *y;
    __nv_bfloat16 *xh, *xl, *ah, *al, *w1h, *w1l, *w2h, *w2l;
    cudaGetSymbolAddress((void**)&qkv, g_qkv);
    cudaGetSymbolAddress((void**)&y, g_y);
    cudaGetSymbolAddress((void**)&xh, g_xh);
    cudaGetSymbolAddress((void**)&xl, g_xl);
    cudaGetSymbolAddress((void**)&ah, g_ah);
    cudaGetSymbolAddress((void**)&al, g_al);
    cudaGetSymbolAddress((void**)&w1h, g_w1h);
    cudaGetSymbolAddress((void**)&w1l, g_w1l);
    cudaGetSymbolAddress((void**)&w2h, g_w2h);
    cudaGetSymbolAddress((void**)&w2l, g_w2l);

    cudaFuncSetAttribute(gemm_mma, cudaFuncAttributeMaxDynamicSharedMemorySize, GEMM_SMEM);

    // 1) splits
    const int n4 = MROWS * CC / 4;
    split_kernel<<<(n4 + 255) / 256, 256>>>(x, xh, xl, n4);
    wsplit_kernel<<<dim3(1536 / 32, 512 / 32), dim3(32, 8)>>>(Wqkv, w1h, w1l, 512, 1536);
    wsplit_kernel<<<dim3(512 / 32, 512 / 32), dim3(32, 8)>>>(Wproj, w2h, w2l, 512, 512);

    // 2) GEMM1: qkv = x @ Wqkv + bqkv
    gemm_mma<<<dim3(1536 / 128, (MROWS + 127) / 128), 256, GEMM_SMEM>>>(
        xh, xl, w1h, w1l, bqkv, nullptr, qkv, MROWS, 1536);

    // 3) attention (writes split output)
    attn_kernel<<<BNF * HH, 64>>>(qkv, ah, al);

    // 4) GEMM2: y = att @ Wproj + bproj + x
    gemm_mma<<<dim3(512 / 128, (MROWS + 127) / 128), 256, GEMM_SMEM>>>(
        ah, al, w2h, w2l, bproj, x, y, MROWS, 512);

    // 5) LayerNorm
    ln_kernel<<<MROWS, 128>>>(y, out);
}

// round 5
// speedup vs baseline: 1.8472x; 1.0750x over previous
#include <cuda_runtime.h>
#include <cuda_bf16.h>
#include <math.h>
#include <stdint.h>

// Problem constants
#define BB 16
#define NN 243
#define JJ 17
#define CC 512
#define HH 8
#define MROWS (BB * NN * JJ)      // 66096
#define BNF   (BB * NN)           // 3888
#define KDIM  512

// Scratch (device globals: allocation-free per harness rules)
__device__ float g_qkv[(size_t)MROWS * 1536];
__device__ float g_y[(size_t)MROWS * CC];
__device__ __nv_bfloat16 g_xh[(size_t)MROWS * CC];
__device__ __nv_bfloat16 g_xl[(size_t)MROWS * CC];
__device__ __nv_bfloat16 g_ah[(size_t)MROWS * CC];
__device__ __nv_bfloat16 g_al[(size_t)MROWS * CC];
__device__ __nv_bfloat16 g_w1h[1536 * 512];   // Wqkv^T split, [N][K]
__device__ __nv_bfloat16 g_w1l[1536 * 512];
__device__ __nv_bfloat16 g_w2h[512 * 512];    // Wproj^T split
__device__ __nv_bfloat16 g_w2l[512 * 512];

// ---------------------------------------------------------------------------
// PTX helpers
// ---------------------------------------------------------------------------
__device__ __forceinline__ uint32_t smem_u32(const void* p) {
    uint32_t a;
    asm("{ .reg .u64 t; cvta.to.shared.u64 t, %1; cvt.u32.u64 %0, t; }"
        : "=r"(a) : "l"(p));
    return a;
}

#define CP_ASYNC16(dst, src, sz) \
    asm volatile("cp.async.cg.shared.global [%0], [%1], 16, %2;\n" \
                 :: "r"((uint32_t)(dst)), "l"(src), "r"(sz))
#define CP_COMMIT() asm volatile("cp.async.commit_group;\n" ::: "memory")
#define CP_WAIT1()  asm volatile("cp.async.wait_group 1;\n" ::: "memory")

#define LDSM4(r0, r1, r2, r3, a) \
    asm volatile("ldmatrix.sync.aligned.m8n8.x4.shared.b16 {%0,%1,%2,%3}, [%4];" \
                 : "=r"(r0), "=r"(r1), "=r"(r2), "=r"(r3) : "r"(a))

__device__ __forceinline__ void mma16816(float* c, const uint32_t* a, const uint32_t* b) {
    asm volatile(
        "mma.sync.aligned.m16n8k16.row.col.f32.bf16.bf16.f32 "
        "{%0,%1,%2,%3}, {%4,%5,%6,%7}, {%8,%9}, {%0,%1,%2,%3};\n"
        : "+f"(c[0]), "+f"(c[1]), "+f"(c[2]), "+f"(c[3])
        : "r"(a[0]), "r"(a[1]), "r"(a[2]), "r"(a[3]), "r"(b[0]), "r"(b[1]));
}

// ---------------------------------------------------------------------------
// Split-bf16 HMMA GEMM: C(MxN) = [Ah+Al](MxK) @ [Bh+Bl]^T(NxK) + bias (+resid)
// BM=128, BN=256, BK=32, 256 threads (8 warps 2x4), warp tile 64x64.
// 3-stage cp.async pipeline; ldmatrix from 80B-padded rows (conflict-free).
// K = 512. M ragged (zero-filled loads, guarded stores). N % 256 == 0.
// ---------------------------------------------------------------------------
#define ROWB 80                        // padded row stride in bytes (40 bf16)
#define ST_AH 0
#define ST_AL (128 * ROWB)             // 10240
#define ST_BH (2 * 128 * ROWB)         // 20480
#define ST_BL (ST_BH + 256 * ROWB)     // 40960
#define STAGE_BYTES (ST_BL + 256 * ROWB)   // 61440
#define NSTAGE 3
#define GEMM_SMEM (NSTAGE * STAGE_BYTES)   // 184320

__device__ __forceinline__ void load_tile(
    uint32_t stage,
    const __nv_bfloat16* __restrict__ Ah, const __nv_bfloat16* __restrict__ Al,
    const __nv_bfloat16* __restrict__ Bh, const __nv_bfloat16* __restrict__ Bl,
    int bm, int bn, int M, int kt, int tid)
{
    const int k0 = kt * 32;
    // A: 128 rows x 4 16B-chunks, hi+lo
#pragma unroll
    for (int i = 0; i < 2; i++) {
        int q = i * 256 + tid;            // 0..511
        int row = q >> 2, c = q & 3;
        uint32_t dof = row * ROWB + c * 16;
        size_t ga = (size_t)(bm + row) * KDIM + k0 + c * 8;
        int p = ((bm + row) < M) ? 16 : 0;
        CP_ASYNC16(stage + ST_AH + dof, Ah + ga, p);
        CP_ASYNC16(stage + ST_AL + dof, Al + ga, p);
    }
    // B: 256 rows x 4 16B-chunks, hi+lo
#pragma unroll
    for (int i = 0; i < 4; i++) {
        int q = i * 256 + tid;            // 0..1023
        int row = q >> 2, c = q & 3;
        uint32_t dof = row * ROWB + c * 16;
        size_t gb = (size_t)(bn + row) * KDIM + k0 + c * 8;
        CP_ASYNC16(stage + ST_BH + dof, Bh + gb, 16);
        CP_ASYNC16(stage + ST_BL + dof, Bl + gb, 16);
    }
}

__global__ void __launch_bounds__(256, 1) gemm_mma(
    const __nv_bfloat16* __restrict__ Ah, const __nv_bfloat16* __restrict__ Al,
    const __nv_bfloat16* __restrict__ Bh, const __nv_bfloat16* __restrict__ Bl,
    const float* __restrict__ bias, const float* __restrict__ resid,
    float* __restrict__ Cm, int M, int N)
{
    extern __shared__ char smem[];
    const uint32_t sb = smem_u32(smem);
    const int tid = threadIdx.x;
    const int w = tid >> 5, lane = tid & 31;
    const int wm = w & 1;                 // 2 warp-rows of 64
    const int wn = w >> 1;                // 4 warp-cols of 64
    const int bn = blockIdx.x << 8;       // BN=256
    const int bm = blockIdx.y << 7;       // BM=128

    float acc[4][8][4];
#pragma unroll
    for (int i = 0; i < 4; i++)
#pragma unroll
        for (int j = 0; j < 8; j++)
#pragma unroll
            for (int e = 0; e < 4; e++) acc[i][j][e] = 0.f;

    const int lrow = lane & 15;
    const int lkb = (lane >> 4) << 4;     // k8-half byte offset
    const uint32_t a_lane_off = (wm * 64 + lrow) * ROWB + lkb;
    const uint32_t b_lane_off = (wn * 64 + lrow) * ROWB + lkb;

    const int T = KDIM / 32;              // 16
    load_tile(sb, Ah, Al, Bh, Bl, bm, bn, M, 0, tid);
    CP_COMMIT();
    load_tile(sb + STAGE_BYTES, Ah, Al, Bh, Bl, bm, bn, M, 1, tid);
    CP_COMMIT();

    int sidx = 0;
    for (int kt = 0; kt < T; kt++) {
        CP_WAIT1();                        // stage kt resident
        __syncthreads();

        if (kt + 2 < T)
            load_tile(sb + ((sidx + 2 >= NSTAGE) ? sidx + 2 - NSTAGE : sidx + 2) * STAGE_BYTES,
                      Ah, Al, Bh, Bl, bm, bn, M, kt + 2, tid);
        CP_COMMIT();

        const uint32_t stage = sb + sidx * STAGE_BYTES;
#pragma unroll
        for (int kc = 0; kc < 2; kc++) {
            const uint32_t kbo = kc * 32;  // 16 bf16 = 32B per k16-chunk
            uint32_t ah[4][4], al[4][4];
#pragma unroll
            for (int mi = 0; mi < 4; mi++) {
                uint32_t ad = stage + a_lane_off + mi * (16 * ROWB) + kbo;
                LDSM4(ah[mi][0], ah[mi][1], ah[mi][2], ah[mi][3], ad + ST_AH);
                LDSM4(al[mi][0], al[mi][1], al[mi][2], al[mi][3], ad + ST_AL);
            }
#pragma unroll
            for (int h2 = 0; h2 < 2; h2++) {       // two halves of 32 n-cols
                uint32_t bh[4][2], bl[4][2];
#pragma unroll
                for (int njj = 0; njj < 2; njj++) {
                    int nj = h2 * 2 + njj;         // n16 tile index (0..3)
                    uint32_t bd = stage + b_lane_off + nj * (16 * ROWB) + kbo;
                    uint32_t h0, h1, h2r, h3, l0, l1, l2, l3;
                    LDSM4(h0, h1, h2r, h3, bd + ST_BH);
                    LDSM4(l0, l1, l2, l3, bd + ST_BL);
                    bh[njj * 2 + 0][0] = h0; bh[njj * 2 + 0][1] = h2r;
                    bh[njj * 2 + 1][0] = h1; bh[njj * 2 + 1][1] = h3;
                    bl[njj * 2 + 0][0] = l0; bl[njj * 2 + 0][1] = l2;
                    bl[njj * 2 + 1][0] = l1; bl[njj * 2 + 1][1] = l3;
                }
#pragma unroll
                for (int mi = 0; mi < 4; mi++)
#pragma unroll
                    for (int nq = 0; nq < 4; nq++) {
                        float* a = acc[mi][h2 * 4 + nq];
                        mma16816(a, ah[mi], bh[nq]);
                        mma16816(a, ah[mi], bl[nq]);
                        mma16816(a, al[mi], bh[nq]);
                    }
            }
        }
        sidx = (sidx + 1 >= NSTAGE) ? 0 : sidx + 1;
    }

    // Epilogue: thread g*4+t holds (m=g, n=2t) and (m=g+8, n=2t) per 16x8 tile
    const int g = lane >> 2, t = lane & 3;
#pragma unroll
    for (int mi = 0; mi < 4; mi++) {
#pragma unroll
        for (int ni = 0; ni < 8; ni++) {
            int col = bn + wn * 64 + ni * 8 + t * 2;
            float bb0 = bias[col], bb1 = bias[col + 1];
            int r0 = bm + wm * 64 + mi * 16 + g;
            if (r0 < M) {
                float2 o;
                o.x = acc[mi][ni][0] + bb0;
                o.y = acc[mi][ni][1] + bb1;
                if (resid) {
                    const float2 rr = *(const float2*)(resid + (size_t)r0 * N + col);
                    o.x += rr.x; o.y += rr.y;
                }
                *(float2*)(Cm + (size_t)r0 * N + col) = o;
            }
            int r1 = r0 + 8;
            if (r1 < M) {
                float2 o;
                o.x = acc[mi][ni][2] + bb0;
                o.y = acc[mi][ni][3] + bb1;
                if (resid) {
                    const float2 rr = *(const float2*)(resid + (size_t)r1 * N + col);
                    o.x += rr.x; o.y += rr.y;
                }
                *(float2*)(Cm + (size_t)r1 * N + col) = o;
            }
        }
    }
}

// ---------------------------------------------------------------------------
// Elementwise fp32 -> bf16 hi/lo split
// ---------------------------------------------------------------------------
__global__ void split_kernel(const float* __restrict__ src,
                             __nv_bfloat16* __restrict__ hi,
                             __nv_bfloat16* __restrict__ lo, int n4) {
    int i = blockIdx.x * blockDim.x + threadIdx.x;
    if (i >= n4) return;
    float4 v = ((const float4*)src)[i];
    __nv_bfloat16 h0 = __float2bfloat16(v.x), h1 = __float2bfloat16(v.y);
    __nv_bfloat16 h2 = __float2bfloat16(v.z), h3 = __float2bfloat16(v.w);
    __nv_bfloat162* hp = (__nv_bfloat162*)hi;
    __nv_bfloat162* lp = (__nv_bfloat162*)lo;
    hp[2 * i]     = __halves2bfloat162(h0, h1);
    hp[2 * i + 1] = __halves2bfloat162(h2, h3);
    lp[2 * i]     = __halves2bfloat162(__float2bfloat16(v.x - __bfloat162float(h0)),
                                       __float2bfloat16(v.y - __bfloat162float(h1)));
    lp[2 * i + 1] = __halves2bfloat162(__float2bfloat16(v.z - __bfloat162float(h2)),
                                       __float2bfloat16(v.w - __bfloat162float(h3)));
}

// Transpose + split: W (KxN row-major) -> hiT/loT (NxK row-major)
__global__ void wsplit_kernel(const float* __restrict__ W,
                              __nv_bfloat16* __restrict__ hiT,
                              __nv_bfloat16* __restrict__ loT, int K, int N) {
    __shared__ float t[32][33];
    const int n0 = blockIdx.x * 32, k0 = blockIdx.y * 32;
    const int tx = threadIdx.x, ty = threadIdx.y;
    for (int r = ty; r < 32; r += 8)
        t[r][tx] = W[(size_t)(k0 + r) * N + n0 + tx];
    __syncthreads();
    for (int r = ty; r < 32; r += 8) {
        float v = t[tx][r];                       // (k0+tx, n0+r)
        __nv_bfloat16 h = __float2bfloat16(v);
        size_t o = (size_t)(n0 + r) * K + k0 + tx;
        hiT[o] = h;
        loT[o] = __float2bfloat16(v - __bfloat162float(h));
    }
}

// ---------------------------------------------------------------------------
// Attention per (frame, head): 17x17, softmax, 13 triplets, P@V. Output split.
// ---------------------------------------------------------------------------
__global__ __launch_bounds__(64)
void attn_kernel(const float* __restrict__ qkv,
                 __nv_bfloat16* __restrict__ oh, __nv_bfloat16* __restrict__ ol) {
    const int bh = blockIdx.x;
    const int bn = bh >> 3;
    const int h  = bh & 7;
    const int d  = threadIdx.x;

    __shared__ float qs[17][64];
    __shared__ float ks[17][64];
    __shared__ float vs[17][64];
    __shared__ float S[17][17];

    const float* base = qkv + (size_t)bn * 17 * 1536 + h * 64;
#pragma unroll
    for (int j = 0; j < 17; j++) {
        const float* r = base + (size_t)j * 1536;
        qs[j][d] = r[d];
        ks[j][d] = r[512 + d];
        vs[j][d] = r[1024 + d];
    }
    __syncthreads();

    for (int idx = d; idx < 289; idx += 64) {
        int i = idx / 17;
        int j = idx - i * 17;
        float s = 0.f;
#pragma unroll
        for (int dd = 0; dd < 64; dd++) s += qs[i][dd] * ks[j][dd];
        S[i][j] = s * 0.125f;
    }
    __syncthreads();

    if (d < 17) {
        float mx = -1e30f;
#pragma unroll
        for (int j = 0; j < 17; j++) mx = fmaxf(mx, S[d][j]);
        float sum = 0.f;
#pragma unroll
        for (int j = 0; j < 17; j++) {
            float e = expf(S[d][j] - mx);
            S[d][j] = e;
            sum += e;
        }
        float inv = 1.f / sum;
#pragma unroll
        for (int j = 0; j < 17; j++) S[d][j] *= inv;
    }
    __syncthreads();

    if (d == 0) {
        const int trip[13][3] = {
            {0,1,2},{1,2,3},{0,4,5},{4,5,6},{0,7,8},{7,8,9},{8,9,10},
            {7,8,11},{8,11,12},{11,12,13},{7,8,14},{8,14,15},{14,15,16}};
#pragma unroll
        for (int tt = 0; tt < 13; tt++) {
            int jp = trip[tt][0], j = trip[tt][1], jc = trip[tt][2];
            float half = S[j][jp] * 0.5f;
            S[j][jc] += half;
            S[jc][j] += half;
        }
    }
    __syncthreads();

#pragma unroll
    for (int i = 0; i < 17; i++) {
        float o = 0.f;
#pragma unroll
        for (int j = 0; j < 17; j++) o += S[i][j] * vs[j][d];
        size_t idx = ((size_t)(bn * 17 + i)) * 512 + h * 64 + d;
        __nv_bfloat16 hh = __float2bfloat16(o);
        oh[idx] = hh;
        ol[idx] = __float2bfloat16(o - __bfloat162float(hh));
    }
}

// ---------------------------------------------------------------------------
// LayerNorm (no affine) over last dim 512
// ---------------------------------------------------------------------------
__global__ __launch_bounds__(128)
void ln_kernel(const float* __restrict__ Y, float* __restrict__ O) {
    const int row = blockIdx.x;
    const int t = threadIdx.x;
    const float4* yp = reinterpret_cast<const float4*>(Y + (size_t)row * 512);
    float4* op = reinterpret_cast<float4*>(O + (size_t)row * 512);

    float4 v = yp[t];
    float s = v.x + v.y + v.z + v.w;
    float q = v.x * v.x + v.y * v.y + v.z * v.z + v.w * v.w;
#pragma unroll
    for (int o = 16; o > 0; o >>= 1) {
        s += __shfl_xor_sync(0xffffffffu, s, o);
        q += __shfl_xor_sync(0xffffffffu, q, o);
    }
    __shared__ float ss[4], sq[4];
    int w = t >> 5;
    if ((t & 31) == 0) { ss[w] = s; sq[w] = q; }
    __syncthreads();
    s = ss[0] + ss[1] + ss[2] + ss[3];
    q = sq[0] + sq[1] + sq[2] + sq[3];

    const float inv512 = 1.f / 512.f;
    float mean = s * inv512;
    float var = q * inv512 - mean * mean;
    float r = rsqrtf(var + 1e-5f);

    float4 o4;
    o4.x = (v.x - mean) * r;
    o4.y = (v.y - mean) * r;
    o4.z = (v.z - mean) * r;
    o4.w = (v.w - mean) * r;
    op[t] = o4;
}

// ---------------------------------------------------------------------------
extern "C" void kernel_launch(void* const* d_in, const int* in_sizes, int n_in,
                              void* d_out, int out_size) {
    const float* x     = (const float*)d_in[0];
    const float* Wqkv  = (const float*)d_in[1];
    const float* bqkv  = (const float*)d_in[2];
    const float* Wproj = (const float*)d_in[3];
    const float* bproj = (const float*)d_in[4];
    float* out = (float*)d_out;

    float *qkv, *y;
    __nv_bfloat16 *xh, *xl, *ah, *al, *w1h, *w1l, *w2h, *w2l;
    cudaGetSymbolAddress((void**)&qkv, g_qkv);
    cudaGetSymbolAddress((void**)&y, g_y);
    cudaGetSymbolAddress((void**)&xh, g_xh);
    cudaGetSymbolAddress((void**)&xl, g_xl);
    cudaGetSymbolAddress((void**)&ah, g_ah);
    cudaGetSymbolAddress((void**)&al, g_al);
    cudaGetSymbolAddress((void**)&w1h, g_w1h);
    cudaGetSymbolAddress((void**)&w1l, g_w1l);
    cudaGetSymbolAddress((void**)&w2h, g_w2h);
    cudaGetSymbolAddress((void**)&w2l, g_w2l);

    cudaFuncSetAttribute(gemm_mma, cudaFuncAttributeMaxDynamicSharedMemorySize, GEMM_SMEM);

    // 1) splits
    const int n4 = MROWS * CC / 4;
    split_kernel<<<(n4 + 255) / 256, 256>>>(x, xh, xl, n4);
    wsplit_kernel<<<dim3(1536 / 32, 512 / 32), dim3(32, 8)>>>(Wqkv, w1h, w1l, 512, 1536);
    wsplit_kernel<<<dim3(512 / 32, 512 / 32), dim3(32, 8)>>>(Wproj, w2h, w2l, 512, 512);

    // 2) GEMM1: qkv = x @ Wqkv + bqkv
    gemm_mma<<<dim3(1536 / 256, (MROWS + 127) / 128), 256, GEMM_SMEM>>>(
        xh, xl, w1h, w1l, bqkv, nullptr, qkv, MROWS, 1536);

    // 3) attention (writes split output)
    attn_kernel<<<BNF * HH, 64>>>(qkv, ah, al);

    // 4) GEMM2: y = att @ Wproj + bproj + x
    gemm_mma<<<dim3(512 / 256, (MROWS + 127) / 128), 256, GEMM_SMEM>>>(
        ah, al, w2h, w2l, bproj, x, y, MROWS, 512);

    // 5) LayerNorm
    ln_kernel<<<MROWS, 128>>>(y, out);
}

// round 6
// speedup vs baseline: 1.8714x; 1.0131x over previous
#include <cuda_runtime.h>
#include <cuda_bf16.h>
#include <math.h>
#include <stdint.h>

// Problem constants
#define BB 16
#define NN 243
#define JJ 17
#define CC 512
#define HH 8
#define MROWS (BB * NN * JJ)      // 66096
#define BNF   (BB * NN)           // 3888
#define KDIM  512

// Scratch (device globals: allocation-free per harness rules)
__device__ float g_qkv[(size_t)MROWS * 1536];
__device__ float g_y[(size_t)MROWS * CC];
__device__ __nv_bfloat16 g_xh[(size_t)MROWS * CC];
__device__ __nv_bfloat16 g_xl[(size_t)MROWS * CC];
__device__ __nv_bfloat16 g_ah[(size_t)MROWS * CC];
__device__ __nv_bfloat16 g_al[(size_t)MROWS * CC];
__device__ __nv_bfloat16 g_w1h[1536 * 512];   // Wqkv^T split, [N][K]
__device__ __nv_bfloat16 g_w1l[1536 * 512];
__device__ __nv_bfloat16 g_w2h[512 * 512];    // Wproj^T split
__device__ __nv_bfloat16 g_w2l[512 * 512];

// ---------------------------------------------------------------------------
// PTX helpers
// ---------------------------------------------------------------------------
__device__ __forceinline__ uint32_t smem_u32(const void* p) {
    uint32_t a;
    asm("{ .reg .u64 t; cvta.to.shared.u64 t, %1; cvt.u32.u64 %0, t; }"
        : "=r"(a) : "l"(p));
    return a;
}

#define CP_ASYNC16(dst, src, sz) \
    asm volatile("cp.async.cg.shared.global [%0], [%1], 16, %2;\n" \
                 :: "r"((uint32_t)(dst)), "l"(src), "r"(sz))
#define CP_COMMIT() asm volatile("cp.async.commit_group;\n" ::: "memory")
#define CP_WAIT1()  asm volatile("cp.async.wait_group 1;\n" ::: "memory")

#define LDSM4(r0, r1, r2, r3, a) \
    asm volatile("ldmatrix.sync.aligned.m8n8.x4.shared.b16 {%0,%1,%2,%3}, [%4];" \
                 : "=r"(r0), "=r"(r1), "=r"(r2), "=r"(r3) : "r"(a))

__device__ __forceinline__ void mma16816(float* c, const uint32_t* a, const uint32_t* b) {
    asm volatile(
        "mma.sync.aligned.m16n8k16.row.col.f32.bf16.bf16.f32 "
        "{%0,%1,%2,%3}, {%4,%5,%6,%7}, {%8,%9}, {%0,%1,%2,%3};\n"
        : "+f"(c[0]), "+f"(c[1]), "+f"(c[2]), "+f"(c[3])
        : "r"(a[0]), "r"(a[1]), "r"(a[2]), "r"(a[3]), "r"(b[0]), "r"(b[1]));
}

// ---------------------------------------------------------------------------
// Split-bf16 HMMA GEMM: C(MxN) = [Ah+Al](MxK) @ [Bh+Bl]^T(NxK) + bias (+resid)
// BM=128, BN=256, BK=32, 512 threads (16 warps 4x4), warp tile 32x64.
// 3-stage cp.async pipeline; ldmatrix from 80B-padded rows (conflict-free).
// K = 512. M ragged (zero-filled loads, guarded stores). N % 256 == 0.
// ---------------------------------------------------------------------------
#define ROWB 80                        // padded row stride in bytes (40 bf16)
#define ST_AH 0
#define ST_AL (128 * ROWB)             // 10240
#define ST_BH (2 * 128 * ROWB)         // 20480
#define ST_BL (ST_BH + 256 * ROWB)     // 40960
#define STAGE_BYTES (ST_BL + 256 * ROWB)   // 61440
#define NSTAGE 3
#define GEMM_SMEM (NSTAGE * STAGE_BYTES)   // 184320

__device__ __forceinline__ void load_tile(
    uint32_t stage,
    const __nv_bfloat16* __restrict__ Ah, const __nv_bfloat16* __restrict__ Al,
    const __nv_bfloat16* __restrict__ Bh, const __nv_bfloat16* __restrict__ Bl,
    int bm, int bn, int M, int kt, int tid)
{
    const int k0 = kt * 32;
    // A: 128 rows x 4 16B-chunks, hi+lo (512 threads -> 1 pass)
    {
        int row = tid >> 2, c = tid & 3;
        uint32_t dof = row * ROWB + c * 16;
        size_t ga = (size_t)(bm + row) * KDIM + k0 + c * 8;
        int p = ((bm + row) < M) ? 16 : 0;
        CP_ASYNC16(stage + ST_AH + dof, Ah + ga, p);
        CP_ASYNC16(stage + ST_AL + dof, Al + ga, p);
    }
    // B: 256 rows x 4 16B-chunks, hi+lo (2 passes)
#pragma unroll
    for (int i = 0; i < 2; i++) {
        int q = i * 512 + tid;
        int row = q >> 2, c = q & 3;
        uint32_t dof = row * ROWB + c * 16;
        size_t gb = (size_t)(bn + row) * KDIM + k0 + c * 8;
        CP_ASYNC16(stage + ST_BH + dof, Bh + gb, 16);
        CP_ASYNC16(stage + ST_BL + dof, Bl + gb, 16);
    }
}

__global__ void __launch_bounds__(512, 1) gemm_mma(
    const __nv_bfloat16* __restrict__ Ah, const __nv_bfloat16* __restrict__ Al,
    const __nv_bfloat16* __restrict__ Bh, const __nv_bfloat16* __restrict__ Bl,
    const float* __restrict__ bias, const float* __restrict__ resid,
    float* __restrict__ Cm, int M, int N)
{
    extern __shared__ char smem[];
    const uint32_t sb = smem_u32(smem);
    const int tid = threadIdx.x;
    const int w = tid >> 5, lane = tid & 31;
    const int wm = w & 3;                 // 4 warp-rows of 32
    const int wn = w >> 2;                // 4 warp-cols of 64
    const int bn = blockIdx.x << 8;       // BN=256
    const int bm = blockIdx.y << 7;       // BM=128

    float acc[2][8][4];
#pragma unroll
    for (int i = 0; i < 2; i++)
#pragma unroll
        for (int j = 0; j < 8; j++)
#pragma unroll
            for (int e = 0; e < 4; e++) acc[i][j][e] = 0.f;

    const int lrow = lane & 15;
    const int lkb = (lane >> 4) << 4;     // k8-half byte offset
    const uint32_t a_lane_off = (wm * 32 + lrow) * ROWB + lkb;
    const uint32_t b_lane_off = (wn * 64 + lrow) * ROWB + lkb;

    const int T = KDIM / 32;              // 16
    load_tile(sb, Ah, Al, Bh, Bl, bm, bn, M, 0, tid);
    CP_COMMIT();
    load_tile(sb + STAGE_BYTES, Ah, Al, Bh, Bl, bm, bn, M, 1, tid);
    CP_COMMIT();

    int sidx = 0;
    for (int kt = 0; kt < T; kt++) {
        CP_WAIT1();                        // stage kt resident
        __syncthreads();

        if (kt + 2 < T)
            load_tile(sb + ((sidx + 2 >= NSTAGE) ? sidx + 2 - NSTAGE : sidx + 2) * STAGE_BYTES,
                      Ah, Al, Bh, Bl, bm, bn, M, kt + 2, tid);
        CP_COMMIT();

        const uint32_t stage = sb + sidx * STAGE_BYTES;
#pragma unroll
        for (int kc = 0; kc < 2; kc++) {
            const uint32_t kbo = kc * 32;  // 16 bf16 = 32B per k16-chunk
            uint32_t ah[2][4], al[2][4];
#pragma unroll
            for (int mi = 0; mi < 2; mi++) {
                uint32_t ad = stage + a_lane_off + mi * (16 * ROWB) + kbo;
                LDSM4(ah[mi][0], ah[mi][1], ah[mi][2], ah[mi][3], ad + ST_AH);
                LDSM4(al[mi][0], al[mi][1], al[mi][2], al[mi][3], ad + ST_AL);
            }
#pragma unroll
            for (int h2 = 0; h2 < 2; h2++) {       // two halves of 32 n-cols
                uint32_t bh[4][2], bl[4][2];
#pragma unroll
                for (int njj = 0; njj < 2; njj++) {
                    int nj = h2 * 2 + njj;         // n16 tile index (0..3)
                    uint32_t bd = stage + b_lane_off + nj * (16 * ROWB) + kbo;
                    uint32_t h0, h1, h2r, h3, l0, l1, l2, l3;
                    LDSM4(h0, h1, h2r, h3, bd + ST_BH);
                    LDSM4(l0, l1, l2, l3, bd + ST_BL);
                    bh[njj * 2 + 0][0] = h0; bh[njj * 2 + 0][1] = h2r;
                    bh[njj * 2 + 1][0] = h1; bh[njj * 2 + 1][1] = h3;
                    bl[njj * 2 + 0][0] = l0; bl[njj * 2 + 0][1] = l2;
                    bl[njj * 2 + 1][0] = l1; bl[njj * 2 + 1][1] = l3;
                }
#pragma unroll
                for (int mi = 0; mi < 2; mi++)
#pragma unroll
                    for (int nq = 0; nq < 4; nq++) {
                        float* a = acc[mi][h2 * 4 + nq];
                        mma16816(a, ah[mi], bh[nq]);
                        mma16816(a, ah[mi], bl[nq]);
                        mma16816(a, al[mi], bh[nq]);
                    }
            }
        }
        sidx = (sidx + 1 >= NSTAGE) ? 0 : sidx + 1;
    }

    // Epilogue: thread g*4+t holds (m=g, n=2t) and (m=g+8, n=2t) per 16x8 tile
    const int g = lane >> 2, t = lane & 3;
#pragma unroll
    for (int mi = 0; mi < 2; mi++) {
#pragma unroll
        for (int ni = 0; ni < 8; ni++) {
            int col = bn + wn * 64 + ni * 8 + t * 2;
            float bb0 = bias[col], bb1 = bias[col + 1];
            int r0 = bm + wm * 32 + mi * 16 + g;
            if (r0 < M) {
                float2 o;
                o.x = acc[mi][ni][0] + bb0;
                o.y = acc[mi][ni][1] + bb1;
                if (resid) {
                    const float2 rr = *(const float2*)(resid + (size_t)r0 * N + col);
                    o.x += rr.x; o.y += rr.y;
                }
                *(float2*)(Cm + (size_t)r0 * N + col) = o;
            }
            int r1 = r0 + 8;
            if (r1 < M) {
                float2 o;
                o.x = acc[mi][ni][2] + bb0;
                o.y = acc[mi][ni][3] + bb1;
                if (resid) {
                    const float2 rr = *(const float2*)(resid + (size_t)r1 * N + col);
                    o.x += rr.x; o.y += rr.y;
                }
                *(float2*)(Cm + (size_t)r1 * N + col) = o;
            }
        }
    }
}

// ---------------------------------------------------------------------------
// Elementwise fp32 -> bf16 hi/lo split
// ---------------------------------------------------------------------------
__global__ void split_kernel(const float* __restrict__ src,
                             __nv_bfloat16* __restrict__ hi,
                             __nv_bfloat16* __restrict__ lo, int n4) {
    int i = blockIdx.x * blockDim.x + threadIdx.x;
    if (i >= n4) return;
    float4 v = ((const float4*)src)[i];
    __nv_bfloat16 h0 = __float2bfloat16(v.x), h1 = __float2bfloat16(v.y);
    __nv_bfloat16 h2 = __float2bfloat16(v.z), h3 = __float2bfloat16(v.w);
    __nv_bfloat162* hp = (__nv_bfloat162*)hi;
    __nv_bfloat162* lp = (__nv_bfloat162*)lo;
    hp[2 * i]     = __halves2bfloat162(h0, h1);
    hp[2 * i + 1] = __halves2bfloat162(h2, h3);
    lp[2 * i]     = __halves2bfloat162(__float2bfloat16(v.x - __bfloat162float(h0)),
                                       __float2bfloat16(v.y - __bfloat162float(h1)));
    lp[2 * i + 1] = __halves2bfloat162(__float2bfloat16(v.z - __bfloat162float(h2)),
                                       __float2bfloat16(v.w - __bfloat162float(h3)));
}

// Transpose + split: W (KxN row-major) -> hiT/loT (NxK row-major)
__global__ void wsplit_kernel(const float* __restrict__ W,
                              __nv_bfloat16* __restrict__ hiT,
                              __nv_bfloat16* __restrict__ loT, int K, int N) {
    __shared__ float t[32][33];
    const int n0 = blockIdx.x * 32, k0 = blockIdx.y * 32;
    const int tx = threadIdx.x, ty = threadIdx.y;
    for (int r = ty; r < 32; r += 8)
        t[r][tx] = W[(size_t)(k0 + r) * N + n0 + tx];
    __syncthreads();
    for (int r = ty; r < 32; r += 8) {
        float v = t[tx][r];                       // (k0+tx, n0+r)
        __nv_bfloat16 h = __float2bfloat16(v);
        size_t o = (size_t)(n0 + r) * K + k0 + tx;
        hiT[o] = h;
        loT[o] = __float2bfloat16(v - __bfloat162float(h));
    }
}

// ---------------------------------------------------------------------------
// Attention: 2 heads per 128-thread block (one 64-thread slice per head).
// 17x17 scores, softmax, 13 triplets, P@V. Output split bf16 hi/lo.
// ---------------------------------------------------------------------------
__global__ __launch_bounds__(128)
void attn_kernel(const float* __restrict__ qkv,
                 __nv_bfloat16* __restrict__ oh, __nv_bfloat16* __restrict__ ol) {
    const int blk = blockIdx.x;           // 0 .. BNF*4-1
    const int bn = blk >> 2;
    const int h  = ((blk & 3) << 1) + (threadIdx.x >> 6);
    const int sl = threadIdx.x >> 6;      // slice 0/1
    const int d  = threadIdx.x & 63;

    __shared__ float qs[2][17][64];
    __shared__ float ks[2][17][64];
    __shared__ float vs[2][17][64];
    __shared__ float S[2][17][17];

    const float* base = qkv + (size_t)bn * 17 * 1536 + h * 64;
#pragma unroll
    for (int j = 0; j < 17; j++) {
        const float* r = base + (size_t)j * 1536;
        qs[sl][j][d] = r[d];
        ks[sl][j][d] = r[512 + d];
        vs[sl][j][d] = r[1024 + d];
    }
    __syncthreads();

    for (int idx = d; idx < 289; idx += 64) {
        int i = idx / 17;
        int j = idx - i * 17;
        float s = 0.f;
#pragma unroll
        for (int dd = 0; dd < 64; dd++) s += qs[sl][i][dd] * ks[sl][j][dd];
        S[sl][i][j] = s * 0.125f;
    }
    __syncthreads();

    if (d < 17) {
        float mx = -1e30f;
#pragma unroll
        for (int j = 0; j < 17; j++) mx = fmaxf(mx, S[sl][d][j]);
        float sum = 0.f;
#pragma unroll
        for (int j = 0; j < 17; j++) {
            float e = expf(S[sl][d][j] - mx);
            S[sl][d][j] = e;
            sum += e;
        }
        float inv = 1.f / sum;
#pragma unroll
        for (int j = 0; j < 17; j++) S[sl][d][j] *= inv;
    }
    __syncthreads();

    if (d == 0) {
        const int trip[13][3] = {
            {0,1,2},{1,2,3},{0,4,5},{4,5,6},{0,7,8},{7,8,9},{8,9,10},
            {7,8,11},{8,11,12},{11,12,13},{7,8,14},{8,14,15},{14,15,16}};
#pragma unroll
        for (int tt = 0; tt < 13; tt++) {
            int jp = trip[tt][0], j = trip[tt][1], jc = trip[tt][2];
            float half = S[sl][j][jp] * 0.5f;
            S[sl][j][jc] += half;
            S[sl][jc][j] += half;
        }
    }
    __syncthreads();

#pragma unroll
    for (int i = 0; i < 17; i++) {
        float o = 0.f;
#pragma unroll
        for (int j = 0; j < 17; j++) o += S[sl][i][j] * vs[sl][j][d];
        size_t idx = ((size_t)(bn * 17 + i)) * 512 + h * 64 + d;
        __nv_bfloat16 hh = __float2bfloat16(o);
        oh[idx] = hh;
        ol[idx] = __float2bfloat16(o - __bfloat162float(hh));
    }
}

// ---------------------------------------------------------------------------
// LayerNorm (no affine) over last dim 512
// ---------------------------------------------------------------------------
__global__ __launch_bounds__(128)
void ln_kernel(const float* __restrict__ Y, float* __restrict__ O) {
    const int row = blockIdx.x;
    const int t = threadIdx.x;
    const float4* yp = reinterpret_cast<const float4*>(Y + (size_t)row * 512);
    float4* op = reinterpret_cast<float4*>(O + (size_t)row * 512);

    float4 v = yp[t];
    float s = v.x + v.y + v.z + v.w;
    float q = v.x * v.x + v.y * v.y + v.z * v.z + v.w * v.w;
#pragma unroll
    for (int o = 16; o > 0; o >>= 1) {
        s += __shfl_xor_sync(0xffffffffu, s, o);
        q += __shfl_xor_sync(0xffffffffu, q, o);
    }
    __shared__ float ss[4], sq[4];
    int w = t >> 5;
    if ((t & 31) == 0) { ss[w] = s; sq[w] = q; }
    __syncthreads();
    s = ss[0] + ss[1] + ss[2] + ss[3];
    q = sq[0] + sq[1] + sq[2] + sq[3];

    const float inv512 = 1.f / 512.f;
    float mean = s * inv512;
    float var = q * inv512 - mean * mean;
    float r = rsqrtf(var + 1e-5f);

    float4 o4;
    o4.x = (v.x - mean) * r;
    o4.y = (v.y - mean) * r;
    o4.z = (v.z - mean) * r;
    o4.w = (v.w - mean) * r;
    op[t] = o4;
}

// ---------------------------------------------------------------------------
extern "C" void kernel_launch(void* const* d_in, const int* in_sizes, int n_in,
                              void* d_out, int out_size) {
    const float* x     = (const float*)d_in[0];
    const float* Wqkv  = (const float*)d_in[1];
    const float* bqkv  = (const float*)d_in[2];
    const float* Wproj = (const float*)d_in[3];
    const float* bproj = (const float*)d_in[4];
    float* out = (float*)d_out;

    float *qkv, *y;
    __nv_bfloat16 *xh, *xl, *ah, *al, *w1h, *w1l, *w2h, *w2l;
    cudaGetSymbolAddress((void**)&qkv, g_qkv);
    cudaGetSymbolAddress((void**)&y, g_y);
    cudaGetSymbolAddress((void**)&xh, g_xh);
    cudaGetSymbolAddress((void**)&xl, g_xl);
    cudaGetSymbolAddress((void**)&ah, g_ah);
    cudaGetSymbolAddress((void**)&al, g_al);
    cudaGetSymbolAddress((void**)&w1h, g_w1h);
    cudaGetSymbolAddress((void**)&w1l, g_w1l);
    cudaGetSymbolAddress((void**)&w2h, g_w2h);
    cudaGetSymbolAddress((void**)&w2l, g_w2l);

    cudaFuncSetAttribute(gemm_mma, cudaFuncAttributeMaxDynamicSharedMemorySize, GEMM_SMEM);

    // 1) splits
    const int n4 = MROWS * CC / 4;
    split_kernel<<<(n4 + 255) / 256, 256>>>(x, xh, xl, n4);
    wsplit_kernel<<<dim3(1536 / 32, 512 / 32), dim3(32, 8)>>>(Wqkv, w1h, w1l, 512, 1536);
    wsplit_kernel<<<dim3(512 / 32, 512 / 32), dim3(32, 8)>>>(Wproj, w2h, w2l, 512, 512);

    // 2) GEMM1: qkv = x @ Wqkv + bqkv
    gemm_mma<<<dim3(1536 / 256, (MROWS + 127) / 128), 512, GEMM_SMEM>>>(
        xh, xl, w1h, w1l, bqkv, nullptr, qkv, MROWS, 1536);

    // 3) attention (writes split output)
    attn_kernel<<<BNF * 4, 128>>>(qkv, ah, al);

    // 4) GEMM2: y = att @ Wproj + bproj + x
    gemm_mma<<<dim3(512 / 256, (MROWS + 127) / 128), 512, GEMM_SMEM>>>(
        ah, al, w2h, w2l, bproj, x, y, MROWS, 512);

    // 5) LayerNorm
    ln_kernel<<<MROWS, 128>>>(y, out);
}

// round 7
// speedup vs baseline: 2.3265x; 1.2432x over previous
#include <cuda_runtime.h>
#include <cuda_bf16.h>
#include <math.h>
#include <stdint.h>

// Problem constants
#define BB 16
#define NN 243
#define JJ 17
#define CC 512
#define HH 8
#define MROWS (BB * NN * JJ)      // 66096
#define BNF   (BB * NN)           // 3888
#define KDIM  512

// Scratch (device globals: allocation-free per harness rules)
__device__ float g_qkv[(size_t)MROWS * 1536];
__device__ float g_y[(size_t)MROWS * CC];
__device__ __nv_bfloat16 g_xh[(size_t)MROWS * CC];
__device__ __nv_bfloat16 g_xl[(size_t)MROWS * CC];
__device__ __nv_bfloat16 g_ah[(size_t)MROWS * CC];
__device__ __nv_bfloat16 g_al[(size_t)MROWS * CC];
__device__ __nv_bfloat16 g_w1h[1536 * 512];   // Wqkv^T split, [N][K]
__device__ __nv_bfloat16 g_w1l[1536 * 512];
__device__ __nv_bfloat16 g_w2h[512 * 512];    // Wproj^T split
__device__ __nv_bfloat16 g_w2l[512 * 512];

// ---------------------------------------------------------------------------
// PTX helpers
// ---------------------------------------------------------------------------
__device__ __forceinline__ uint32_t smem_u32(const void* p) {
    uint32_t a;
    asm("{ .reg .u64 t; cvta.to.shared.u64 t, %1; cvt.u32.u64 %0, t; }"
        : "=r"(a) : "l"(p));
    return a;
}

#define CP_ASYNC16(dst, src, sz) \
    asm volatile("cp.async.cg.shared.global [%0], [%1], 16, %2;\n" \
                 :: "r"((uint32_t)(dst)), "l"(src), "r"(sz))
#define CP_COMMIT() asm volatile("cp.async.commit_group;\n" ::: "memory")
#define CP_WAIT1()  asm volatile("cp.async.wait_group 1;\n" ::: "memory")

#define LDSM4(r0, r1, r2, r3, a) \
    asm volatile("ldmatrix.sync.aligned.m8n8.x4.shared.b16 {%0,%1,%2,%3}, [%4];" \
                 : "=r"(r0), "=r"(r1), "=r"(r2), "=r"(r3) : "r"(a))

__device__ __forceinline__ void mma16816(float* c, const uint32_t* a, const uint32_t* b) {
    asm volatile(
        "mma.sync.aligned.m16n8k16.row.col.f32.bf16.bf16.f32 "
        "{%0,%1,%2,%3}, {%4,%5,%6,%7}, {%8,%9}, {%0,%1,%2,%3};\n"
        : "+f"(c[0]), "+f"(c[1]), "+f"(c[2]), "+f"(c[3])
        : "r"(a[0]), "r"(a[1]), "r"(a[2]), "r"(a[3]), "r"(b[0]), "r"(b[1]));
}

// ---------------------------------------------------------------------------
// Split-bf16 HMMA GEMM: C(MxN) = [Ah+Al](MxK) @ [Bh+Bl]^T(NxK) + bias (+resid)
// BM=128, BN=256, BK=32, 512 threads (16 warps 4x4), warp tile 32x64.
// 3-stage cp.async pipeline; ldmatrix from 80B-padded rows (conflict-free).
// K = 512. M ragged (zero-filled loads, guarded stores). N % 256 == 0.
// ---------------------------------------------------------------------------
#define ROWB 80                        // padded row stride in bytes (40 bf16)
#define ST_AH 0
#define ST_AL (128 * ROWB)             // 10240
#define ST_BH (2 * 128 * ROWB)         // 20480
#define ST_BL (ST_BH + 256 * ROWB)     // 40960
#define STAGE_BYTES (ST_BL + 256 * ROWB)   // 61440
#define NSTAGE 3
#define GEMM_SMEM (NSTAGE * STAGE_BYTES)   // 184320

__device__ __forceinline__ void load_tile(
    uint32_t stage,
    const __nv_bfloat16* __restrict__ Ah, const __nv_bfloat16* __restrict__ Al,
    const __nv_bfloat16* __restrict__ Bh, const __nv_bfloat16* __restrict__ Bl,
    int bm, int bn, int M, int kt, int tid)
{
    const int k0 = kt * 32;
    // A: 128 rows x 4 16B-chunks, hi+lo (512 threads -> 1 pass)
    {
        int row = tid >> 2, c = tid & 3;
        uint32_t dof = row * ROWB + c * 16;
        size_t ga = (size_t)(bm + row) * KDIM + k0 + c * 8;
        int p = ((bm + row) < M) ? 16 : 0;
        CP_ASYNC16(stage + ST_AH + dof, Ah + ga, p);
        CP_ASYNC16(stage + ST_AL + dof, Al + ga, p);
    }
    // B: 256 rows x 4 16B-chunks, hi+lo (2 passes)
#pragma unroll
    for (int i = 0; i < 2; i++) {
        int q = i * 512 + tid;
        int row = q >> 2, c = q & 3;
        uint32_t dof = row * ROWB + c * 16;
        size_t gb = (size_t)(bn + row) * KDIM + k0 + c * 8;
        CP_ASYNC16(stage + ST_BH + dof, Bh + gb, 16);
        CP_ASYNC16(stage + ST_BL + dof, Bl + gb, 16);
    }
}

__global__ void __launch_bounds__(512, 1) gemm_mma(
    const __nv_bfloat16* __restrict__ Ah, const __nv_bfloat16* __restrict__ Al,
    const __nv_bfloat16* __restrict__ Bh, const __nv_bfloat16* __restrict__ Bl,
    const float* __restrict__ bias, const float* __restrict__ resid,
    float* __restrict__ Cm, int M, int N)
{
    extern __shared__ char smem[];
    const uint32_t sb = smem_u32(smem);
    const int tid = threadIdx.x;
    const int w = tid >> 5, lane = tid & 31;
    const int wm = w & 3;                 // 4 warp-rows of 32
    const int wn = w >> 2;                // 4 warp-cols of 64
    const int bn = blockIdx.x << 8;       // BN=256
    const int bm = blockIdx.y << 7;       // BM=128

    float acc[2][8][4];
#pragma unroll
    for (int i = 0; i < 2; i++)
#pragma unroll
        for (int j = 0; j < 8; j++)
#pragma unroll
            for (int e = 0; e < 4; e++) acc[i][j][e] = 0.f;

    const int lrow = lane & 15;
    const int lkb = (lane >> 4) << 4;     // k8-half byte offset
    const uint32_t a_lane_off = (wm * 32 + lrow) * ROWB + lkb;
    const uint32_t b_lane_off = (wn * 64 + lrow) * ROWB + lkb;

    const int T = KDIM / 32;              // 16
    load_tile(sb, Ah, Al, Bh, Bl, bm, bn, M, 0, tid);
    CP_COMMIT();
    load_tile(sb + STAGE_BYTES, Ah, Al, Bh, Bl, bm, bn, M, 1, tid);
    CP_COMMIT();

    int sidx = 0;
    for (int kt = 0; kt < T; kt++) {
        CP_WAIT1();                        // stage kt resident
        __syncthreads();

        if (kt + 2 < T)
            load_tile(sb + ((sidx + 2 >= NSTAGE) ? sidx + 2 - NSTAGE : sidx + 2) * STAGE_BYTES,
                      Ah, Al, Bh, Bl, bm, bn, M, kt + 2, tid);
        CP_COMMIT();

        const uint32_t stage = sb + sidx * STAGE_BYTES;
#pragma unroll
        for (int kc = 0; kc < 2; kc++) {
            const uint32_t kbo = kc * 32;  // 16 bf16 = 32B per k16-chunk
            uint32_t ah[2][4], al[2][4];
#pragma unroll
            for (int mi = 0; mi < 2; mi++) {
                uint32_t ad = stage + a_lane_off + mi * (16 * ROWB) + kbo;
                LDSM4(ah[mi][0], ah[mi][1], ah[mi][2], ah[mi][3], ad + ST_AH);
                LDSM4(al[mi][0], al[mi][1], al[mi][2], al[mi][3], ad + ST_AL);
            }
#pragma unroll
            for (int h2 = 0; h2 < 2; h2++) {       // two halves of 32 n-cols
                uint32_t bh[4][2], bl[4][2];
#pragma unroll
                for (int njj = 0; njj < 2; njj++) {
                    int nj = h2 * 2 + njj;         // n16 tile index (0..3)
                    uint32_t bd = stage + b_lane_off + nj * (16 * ROWB) + kbo;
                    uint32_t h0, h1, h2r, h3, l0, l1, l2, l3;
                    LDSM4(h0, h1, h2r, h3, bd + ST_BH);
                    LDSM4(l0, l1, l2, l3, bd + ST_BL);
                    bh[njj * 2 + 0][0] = h0; bh[njj * 2 + 0][1] = h2r;
                    bh[njj * 2 + 1][0] = h1; bh[njj * 2 + 1][1] = h3;
                    bl[njj * 2 + 0][0] = l0; bl[njj * 2 + 0][1] = l2;
                    bl[njj * 2 + 1][0] = l1; bl[njj * 2 + 1][1] = l3;
                }
#pragma unroll
                for (int mi = 0; mi < 2; mi++)
#pragma unroll
                    for (int nq = 0; nq < 4; nq++) {
                        float* a = acc[mi][h2 * 4 + nq];
                        mma16816(a, ah[mi], bh[nq]);
                        mma16816(a, ah[mi], bl[nq]);
                        mma16816(a, al[mi], bh[nq]);
                    }
            }
        }
        sidx = (sidx + 1 >= NSTAGE) ? 0 : sidx + 1;
    }

    // Epilogue: thread g*4+t holds (m=g, n=2t) and (m=g+8, n=2t) per 16x8 tile
    const int g = lane >> 2, t = lane & 3;
#pragma unroll
    for (int mi = 0; mi < 2; mi++) {
#pragma unroll
        for (int ni = 0; ni < 8; ni++) {
            int col = bn + wn * 64 + ni * 8 + t * 2;
            float bb0 = bias[col], bb1 = bias[col + 1];
            int r0 = bm + wm * 32 + mi * 16 + g;
            if (r0 < M) {
                float2 o;
                o.x = acc[mi][ni][0] + bb0;
                o.y = acc[mi][ni][1] + bb1;
                if (resid) {
                    const float2 rr = *(const float2*)(resid + (size_t)r0 * N + col);
                    o.x += rr.x; o.y += rr.y;
                }
                *(float2*)(Cm + (size_t)r0 * N + col) = o;
            }
            int r1 = r0 + 8;
            if (r1 < M) {
                float2 o;
                o.x = acc[mi][ni][2] + bb0;
                o.y = acc[mi][ni][3] + bb1;
                if (resid) {
                    const float2 rr = *(const float2*)(resid + (size_t)r1 * N + col);
                    o.x += rr.x; o.y += rr.y;
                }
                *(float2*)(Cm + (size_t)r1 * N + col) = o;
            }
        }
    }
}

// ---------------------------------------------------------------------------
// Elementwise fp32 -> bf16 hi/lo split
// ---------------------------------------------------------------------------
__global__ void split_kernel(const float* __restrict__ src,
                             __nv_bfloat16* __restrict__ hi,
                             __nv_bfloat16* __restrict__ lo, int n4) {
    int i = blockIdx.x * blockDim.x + threadIdx.x;
    if (i >= n4) return;
    float4 v = ((const float4*)src)[i];
    __nv_bfloat16 h0 = __float2bfloat16(v.x), h1 = __float2bfloat16(v.y);
    __nv_bfloat16 h2 = __float2bfloat16(v.z), h3 = __float2bfloat16(v.w);
    __nv_bfloat162* hp = (__nv_bfloat162*)hi;
    __nv_bfloat162* lp = (__nv_bfloat162*)lo;
    hp[2 * i]     = __halves2bfloat162(h0, h1);
    hp[2 * i + 1] = __halves2bfloat162(h2, h3);
    lp[2 * i]     = __halves2bfloat162(__float2bfloat16(v.x - __bfloat162float(h0)),
                                       __float2bfloat16(v.y - __bfloat162float(h1)));
    lp[2 * i + 1] = __halves2bfloat162(__float2bfloat16(v.z - __bfloat162float(h2)),
                                       __float2bfloat16(v.w - __bfloat162float(h3)));
}

// Transpose + split: W (KxN row-major) -> hiT/loT (NxK row-major)
__global__ void wsplit_kernel(const float* __restrict__ W,
                              __nv_bfloat16* __restrict__ hiT,
                              __nv_bfloat16* __restrict__ loT, int K, int N) {
    __shared__ float t[32][33];
    const int n0 = blockIdx.x * 32, k0 = blockIdx.y * 32;
    const int tx = threadIdx.x, ty = threadIdx.y;
    for (int r = ty; r < 32; r += 8)
        t[r][tx] = W[(size_t)(k0 + r) * N + n0 + tx];
    __syncthreads();
    for (int r = ty; r < 32; r += 8) {
        float v = t[tx][r];                       // (k0+tx, n0+r)
        __nv_bfloat16 h = __float2bfloat16(v);
        size_t o = (size_t)(n0 + r) * K + k0 + tx;
        hiT[o] = h;
        loT[o] = __float2bfloat16(v - __bfloat162float(h));
    }
}

// ---------------------------------------------------------------------------
// Attention: 2 heads per 128-thread block. Row stride padded to 65 floats:
// score-phase column reads ks[j][dd] hit banks (j+dd)%32 -> conflict-free
// (was 17-way conflict at stride 64).
// ---------------------------------------------------------------------------
#define APAD 65
__global__ __launch_bounds__(128)
void attn_kernel(const float* __restrict__ qkv,
                 __nv_bfloat16* __restrict__ oh, __nv_bfloat16* __restrict__ ol) {
    const int blk = blockIdx.x;           // 0 .. BNF*4-1
    const int bn = blk >> 2;
    const int h  = ((blk & 3) << 1) + (threadIdx.x >> 6);
    const int sl = threadIdx.x >> 6;      // slice 0/1
    const int d  = threadIdx.x & 63;

    __shared__ float qs[2][17][APAD];
    __shared__ float ks[2][17][APAD];
    __shared__ float vs[2][17][APAD];
    __shared__ float S[2][17][17];

    const float* base = qkv + (size_t)bn * 17 * 1536 + h * 64;
#pragma unroll
    for (int j = 0; j < 17; j++) {
        const float* r = base + (size_t)j * 1536;
        qs[sl][j][d] = r[d];
        ks[sl][j][d] = r[512 + d];
        vs[sl][j][d] = r[1024 + d];
    }
    __syncthreads();

    for (int idx = d; idx < 289; idx += 64) {
        int i = idx / 17;
        int j = idx - i * 17;
        float s = 0.f;
#pragma unroll
        for (int dd = 0; dd < 64; dd++) s += qs[sl][i][dd] * ks[sl][j][dd];
        S[sl][i][j] = s * 0.125f;
    }
    __syncthreads();

    if (d < 17) {
        float mx = -1e30f;
#pragma unroll
        for (int j = 0; j < 17; j++) mx = fmaxf(mx, S[sl][d][j]);
        float sum = 0.f;
#pragma unroll
        for (int j = 0; j < 17; j++) {
            float e = expf(S[sl][d][j] - mx);
            S[sl][d][j] = e;
            sum += e;
        }
        float inv = 1.f / sum;
#pragma unroll
        for (int j = 0; j < 17; j++) S[sl][d][j] *= inv;
    }
    __syncthreads();

    if (d == 0) {
        const int trip[13][3] = {
            {0,1,2},{1,2,3},{0,4,5},{4,5,6},{0,7,8},{7,8,9},{8,9,10},
            {7,8,11},{8,11,12},{11,12,13},{7,8,14},{8,14,15},{14,15,16}};
#pragma unroll
        for (int tt = 0; tt < 13; tt++) {
            int jp = trip[tt][0], j = trip[tt][1], jc = trip[tt][2];
            float half = S[sl][j][jp] * 0.5f;
            S[sl][j][jc] += half;
            S[sl][jc][j] += half;
        }
    }
    __syncthreads();

#pragma unroll
    for (int i = 0; i < 17; i++) {
        float o = 0.f;
#pragma unroll
        for (int j = 0; j < 17; j++) o += S[sl][i][j] * vs[sl][j][d];
        size_t idx = ((size_t)(bn * 17 + i)) * 512 + h * 64 + d;
        __nv_bfloat16 hh = __float2bfloat16(o);
        oh[idx] = hh;
        ol[idx] = __float2bfloat16(o - __bfloat162float(hh));
    }
}

// ---------------------------------------------------------------------------
// LayerNorm (no affine) over last dim 512
// ---------------------------------------------------------------------------
__global__ __launch_bounds__(128)
void ln_kernel(const float* __restrict__ Y, float* __restrict__ O) {
    const int row = blockIdx.x;
    const int t = threadIdx.x;
    const float4* yp = reinterpret_cast<const float4*>(Y + (size_t)row * 512);
    float4* op = reinterpret_cast<float4*>(O + (size_t)row * 512);

    float4 v = yp[t];
    float s = v.x + v.y + v.z + v.w;
    float q = v.x * v.x + v.y * v.y + v.z * v.z + v.w * v.w;
#pragma unroll
    for (int o = 16; o > 0; o >>= 1) {
        s += __shfl_xor_sync(0xffffffffu, s, o);
        q += __shfl_xor_sync(0xffffffffu, q, o);
    }
    __shared__ float ss[4], sq[4];
    int w = t >> 5;
    if ((t & 31) == 0) { ss[w] = s; sq[w] = q; }
    __syncthreads();
    s = ss[0] + ss[1] + ss[2] + ss[3];
    q = sq[0] + sq[1] + sq[2] + sq[3];

    const float inv512 = 1.f / 512.f;
    float mean = s * inv512;
    float var = q * inv512 - mean * mean;
    float r = rsqrtf(var + 1e-5f);

    float4 o4;
    o4.x = (v.x - mean) * r;
    o4.y = (v.y - mean) * r;
    o4.z = (v.z - mean) * r;
    o4.w = (v.w - mean) * r;
    op[t] = o4;
}

// ---------------------------------------------------------------------------
extern "C" void kernel_launch(void* const* d_in, const int* in_sizes, int n_in,
                              void* d_out, int out_size) {
    const float* x     = (const float*)d_in[0];
    const float* Wqkv  = (const float*)d_in[1];
    const float* bqkv  = (const float*)d_in[2];
    const float* Wproj = (const float*)d_in[3];
    const float* bproj = (const float*)d_in[4];
    float* out = (float*)d_out;

    float *qkv, *y;
    __nv_bfloat16 *xh, *xl, *ah, *al, *w1h, *w1l, *w2h, *w2l;
    cudaGetSymbolAddress((void**)&qkv, g_qkv);
    cudaGetSymbolAddress((void**)&y, g_y);
    cudaGetSymbolAddress((void**)&xh, g_xh);
    cudaGetSymbolAddress((void**)&xl, g_xl);
    cudaGetSymbolAddress((void**)&ah, g_ah);
    cudaGetSymbolAddress((void**)&al, g_al);
    cudaGetSymbolAddress((void**)&w1h, g_w1h);
    cudaGetSymbolAddress((void**)&w1l, g_w1l);
    cudaGetSymbolAddress((void**)&w2h, g_w2h);
    cudaGetSymbolAddress((void**)&w2l, g_w2l);

    cudaFuncSetAttribute(gemm_mma, cudaFuncAttributeMaxDynamicSharedMemorySize, GEMM_SMEM);

    // 1) splits
    const int n4 = MROWS * CC / 4;
    split_kernel<<<(n4 + 255) / 256, 256>>>(x, xh, xl, n4);
    wsplit_kernel<<<dim3(1536 / 32, 512 / 32), dim3(32, 8)>>>(Wqkv, w1h, w1l, 512, 1536);
    wsplit_kernel<<<dim3(512 / 32, 512 / 32), dim3(32, 8)>>>(Wproj, w2h, w2l, 512, 512);

    // 2) GEMM1: qkv = x @ Wqkv + bqkv
    gemm_mma<<<dim3(1536 / 256, (MROWS + 127) / 128), 512, GEMM_SMEM>>>(
        xh, xl, w1h, w1l, bqkv, nullptr, qkv, MROWS, 1536);

    // 3) attention (writes split output)
    attn_kernel<<<BNF * 4, 128>>>(qkv, ah, al);

    // 4) GEMM2: y = att @ Wproj + bproj + x
    gemm_mma<<<dim3(512 / 256, (MROWS + 127) / 128), 512, GEMM_SMEM>>>(
        ah, al, w2h, w2l, bproj, x, y, MROWS, 512);

    // 5) LayerNorm
    ln_kernel<<<MROWS, 128>>>(y, out);
}

// round 8
// speedup vs baseline: 2.9624x; 1.2733x over previous
#include <cuda_runtime.h>
#include <cuda_fp16.h>
#include <math.h>
#include <stdint.h>

// Problem constants
#define BB 16
#define NN 243
#define JJ 17
#define CC 512
#define HH 8
#define MROWS (BB * NN * JJ)      // 66096
#define BNF   (BB * NN)           // 3888
#define KDIM  512

// Scratch (device globals: allocation-free per harness rules)
__device__ float g_qkv[(size_t)MROWS * 1536];
__device__ float g_y[(size_t)MROWS * CC];
__device__ __half g_xh[(size_t)MROWS * CC];
__device__ __half g_xl[(size_t)MROWS * CC];
__device__ __half g_ah[(size_t)MROWS * CC];
__device__ __half g_al[(size_t)MROWS * CC];
__device__ __half g_w1h[1536 * 512];   // Wqkv^T fp16, [N][K]
__device__ __half g_w2h[512 * 512];    // Wproj^T fp16

// ---------------------------------------------------------------------------
// PTX helpers
// ---------------------------------------------------------------------------
__device__ __forceinline__ uint32_t smem_u32(const void* p) {
    uint32_t a;
    asm("{ .reg .u64 t; cvta.to.shared.u64 t, %1; cvt.u32.u64 %0, t; }"
        : "=r"(a) : "l"(p));
    return a;
}

#define CP_ASYNC16(dst, src, sz) \
    asm volatile("cp.async.cg.shared.global [%0], [%1], 16, %2;\n" \
                 :: "r"((uint32_t)(dst)), "l"(src), "r"(sz))
#define CP_COMMIT() asm volatile("cp.async.commit_group;\n" ::: "memory")
#define CP_WAIT1()  asm volatile("cp.async.wait_group 1;\n" ::: "memory")

#define LDSM4(r0, r1, r2, r3, a) \
    asm volatile("ldmatrix.sync.aligned.m8n8.x4.shared.b16 {%0,%1,%2,%3}, [%4];" \
                 : "=r"(r0), "=r"(r1), "=r"(r2), "=r"(r3) : "r"(a))

__device__ __forceinline__ void mma16816(float* c, const uint32_t* a, const uint32_t* b) {
    asm volatile(
        "mma.sync.aligned.m16n8k16.row.col.f32.f16.f16.f32 "
        "{%0,%1,%2,%3}, {%4,%5,%6,%7}, {%8,%9}, {%0,%1,%2,%3};\n"
        : "+f"(c[0]), "+f"(c[1]), "+f"(c[2]), "+f"(c[3])
        : "r"(a[0]), "r"(a[1]), "r"(a[2]), "r"(a[3]), "r"(b[0]), "r"(b[1]));
}

// ---------------------------------------------------------------------------
// Double-fp16 HMMA GEMM: C(MxN) = (Ah+Al)(MxK) @ Bh^T(NxK) + bias (+resid)
// A split into two fp16 (exact to ~2^-24); B plain fp16 (error ~2^-12, the
// only error source; fp32 accumulate). 2 MMAs per tile position.
// BM=128, BN=256, BK=32, 512 threads (16 warps 4x4), warp tile 32x64.
// 3-stage cp.async pipeline; ldmatrix from 80B-padded rows (conflict-free).
// ---------------------------------------------------------------------------
#define ROWB 80                        // padded row stride in bytes (40 fp16)
#define ST_AH 0
#define ST_AL (128 * ROWB)             // 10240
#define ST_BH (2 * 128 * ROWB)         // 20480
#define STAGE_BYTES (ST_BH + 256 * ROWB)   // 40960
#define NSTAGE 3
#define GEMM_SMEM (NSTAGE * STAGE_BYTES)   // 122880

__device__ __forceinline__ void load_tile(
    uint32_t stage,
    const __half* __restrict__ Ah, const __half* __restrict__ Al,
    const __half* __restrict__ Bh,
    int bm, int bn, int M, int kt, int tid)
{
    const int k0 = kt * 32;
    // A: 128 rows x 4 16B-chunks, hi+lo (512 threads -> 1 pass)
    {
        int row = tid >> 2, c = tid & 3;
        uint32_t dof = row * ROWB + c * 16;
        size_t ga = (size_t)(bm + row) * KDIM + k0 + c * 8;
        int p = ((bm + row) < M) ? 16 : 0;
        CP_ASYNC16(stage + ST_AH + dof, Ah + ga, p);
        CP_ASYNC16(stage + ST_AL + dof, Al + ga, p);
    }
    // B: 256 rows x 4 16B-chunks, hi only (2 passes)
#pragma unroll
    for (int i = 0; i < 2; i++) {
        int q = i * 512 + tid;
        int row = q >> 2, c = q & 3;
        uint32_t dof = row * ROWB + c * 16;
        size_t gb = (size_t)(bn + row) * KDIM + k0 + c * 8;
        CP_ASYNC16(stage + ST_BH + dof, Bh + gb, 16);
    }
}

__global__ void __launch_bounds__(512, 1) gemm_mma(
    const __half* __restrict__ Ah, const __half* __restrict__ Al,
    const __half* __restrict__ Bh,
    const float* __restrict__ bias, const float* __restrict__ resid,
    float* __restrict__ Cm, int M, int N)
{
    extern __shared__ char smem[];
    const uint32_t sb = smem_u32(smem);
    const int tid = threadIdx.x;
    const int w = tid >> 5, lane = tid & 31;
    const int wm = w & 3;                 // 4 warp-rows of 32
    const int wn = w >> 2;                // 4 warp-cols of 64
    const int bn = blockIdx.x << 8;       // BN=256
    const int bm = blockIdx.y << 7;       // BM=128

    float acc[2][8][4];
#pragma unroll
    for (int i = 0; i < 2; i++)
#pragma unroll
        for (int j = 0; j < 8; j++)
#pragma unroll
            for (int e = 0; e < 4; e++) acc[i][j][e] = 0.f;

    const int lrow = lane & 15;
    const int lkb = (lane >> 4) << 4;     // k8-half byte offset
    const uint32_t a_lane_off = (wm * 32 + lrow) * ROWB + lkb;
    const uint32_t b_lane_off = (wn * 64 + lrow) * ROWB + lkb;

    const int T = KDIM / 32;              // 16
    load_tile(sb, Ah, Al, Bh, bm, bn, M, 0, tid);
    CP_COMMIT();
    load_tile(sb + STAGE_BYTES, Ah, Al, Bh, bm, bn, M, 1, tid);
    CP_COMMIT();

    int sidx = 0;
    for (int kt = 0; kt < T; kt++) {
        CP_WAIT1();                        // stage kt resident
        __syncthreads();

        if (kt + 2 < T)
            load_tile(sb + ((sidx + 2 >= NSTAGE) ? sidx + 2 - NSTAGE : sidx + 2) * STAGE_BYTES,
                      Ah, Al, Bh, bm, bn, M, kt + 2, tid);
        CP_COMMIT();

        const uint32_t stage = sb + sidx * STAGE_BYTES;
#pragma unroll
        for (int kc = 0; kc < 2; kc++) {
            const uint32_t kbo = kc * 32;  // 16 fp16 = 32B per k16-chunk
            uint32_t ah[2][4], al[2][4];
#pragma unroll
            for (int mi = 0; mi < 2; mi++) {
                uint32_t ad = stage + a_lane_off + mi * (16 * ROWB) + kbo;
                LDSM4(ah[mi][0], ah[mi][1], ah[mi][2], ah[mi][3], ad + ST_AH);
                LDSM4(al[mi][0], al[mi][1], al[mi][2], al[mi][3], ad + ST_AL);
            }
#pragma unroll
            for (int h2 = 0; h2 < 2; h2++) {       // two halves of 32 n-cols
                uint32_t bh[4][2];
#pragma unroll
                for (int njj = 0; njj < 2; njj++) {
                    int nj = h2 * 2 + njj;         // n16 tile index (0..3)
                    uint32_t bd = stage + b_lane_off + nj * (16 * ROWB) + kbo;
                    uint32_t h0, h1, h2r, h3;
                    LDSM4(h0, h1, h2r, h3, bd + ST_BH);
                    bh[njj * 2 + 0][0] = h0; bh[njj * 2 + 0][1] = h2r;
                    bh[njj * 2 + 1][0] = h1; bh[njj * 2 + 1][1] = h3;
                }
#pragma unroll
                for (int mi = 0; mi < 2; mi++)
#pragma unroll
                    for (int nq = 0; nq < 4; nq++) {
                        float* a = acc[mi][h2 * 4 + nq];
                        mma16816(a, ah[mi], bh[nq]);
                        mma16816(a, al[mi], bh[nq]);
                    }
            }
        }
        sidx = (sidx + 1 >= NSTAGE) ? 0 : sidx + 1;
    }

    // Epilogue: thread g*4+t holds (m=g, n=2t) and (m=g+8, n=2t) per 16x8 tile
    const int g = lane >> 2, t = lane & 3;
#pragma unroll
    for (int mi = 0; mi < 2; mi++) {
#pragma unroll
        for (int ni = 0; ni < 8; ni++) {
            int col = bn + wn * 64 + ni * 8 + t * 2;
            float bb0 = bias[col], bb1 = bias[col + 1];
            int r0 = bm + wm * 32 + mi * 16 + g;
            if (r0 < M) {
                float2 o;
                o.x = acc[mi][ni][0] + bb0;
                o.y = acc[mi][ni][1] + bb1;
                if (resid) {
                    const float2 rr = *(const float2*)(resid + (size_t)r0 * N + col);
                    o.x += rr.x; o.y += rr.y;
                }
                *(float2*)(Cm + (size_t)r0 * N + col) = o;
            }
            int r1 = r0 + 8;
            if (r1 < M) {
                float2 o;
                o.x = acc[mi][ni][2] + bb0;
                o.y = acc[mi][ni][3] + bb1;
                if (resid) {
                    const float2 rr = *(const float2*)(resid + (size_t)r1 * N + col);
                    o.x += rr.x; o.y += rr.y;
                }
                *(float2*)(Cm + (size_t)r1 * N + col) = o;
            }
        }
    }
}

// ---------------------------------------------------------------------------
// Elementwise fp32 -> fp16 hi/lo split
// ---------------------------------------------------------------------------
__global__ void split_kernel(const float* __restrict__ src,
                             __half* __restrict__ hi,
                             __half* __restrict__ lo, int n4) {
    int i = blockIdx.x * blockDim.x + threadIdx.x;
    if (i >= n4) return;
    float4 v = ((const float4*)src)[i];
    __half h0 = __float2half(v.x), h1 = __float2half(v.y);
    __half h2 = __float2half(v.z), h3 = __float2half(v.w);
    __half2* hp = (__half2*)hi;
    __half2* lp = (__half2*)lo;
    hp[2 * i]     = __halves2half2(h0, h1);
    hp[2 * i + 1] = __halves2half2(h2, h3);
    lp[2 * i]     = __halves2half2(__float2half(v.x - __half2float(h0)),
                                   __float2half(v.y - __half2float(h1)));
    lp[2 * i + 1] = __halves2half2(__float2half(v.z - __half2float(h2)),
                                   __float2half(v.w - __half2float(h3)));
}

// Transpose to fp16: W (KxN row-major) -> hiT (NxK row-major)
__global__ void wsplit_kernel(const float* __restrict__ W,
                              __half* __restrict__ hiT, int K, int N) {
    __shared__ float t[32][33];
    const int n0 = blockIdx.x * 32, k0 = blockIdx.y * 32;
    const int tx = threadIdx.x, ty = threadIdx.y;
    for (int r = ty; r < 32; r += 8)
        t[r][tx] = W[(size_t)(k0 + r) * N + n0 + tx];
    __syncthreads();
    for (int r = ty; r < 32; r += 8) {
        float v = t[tx][r];                       // (k0+tx, n0+r)
        hiT[(size_t)(n0 + r) * K + k0 + tx] = __float2half(v);
    }
}

// ---------------------------------------------------------------------------
// Attention: 2 heads per 128-thread block. Row stride padded to 65 floats
// (conflict-free column reads). Output split to fp16 hi/lo.
// ---------------------------------------------------------------------------
#define APAD 65
__global__ __launch_bounds__(128)
void attn_kernel(const float* __restrict__ qkv,
                 __half* __restrict__ oh, __half* __restrict__ ol) {
    const int blk = blockIdx.x;           // 0 .. BNF*4-1
    const int bn = blk >> 2;
    const int h  = ((blk & 3) << 1) + (threadIdx.x >> 6);
    const int sl = threadIdx.x >> 6;      // slice 0/1
    const int d  = threadIdx.x & 63;

    __shared__ float qs[2][17][APAD];
    __shared__ float ks[2][17][APAD];
    __shared__ float vs[2][17][APAD];
    __shared__ float S[2][17][17];

    const float* base = qkv + (size_t)bn * 17 * 1536 + h * 64;
#pragma unroll
    for (int j = 0; j < 17; j++) {
        const float* r = base + (size_t)j * 1536;
        qs[sl][j][d] = r[d];
        ks[sl][j][d] = r[512 + d];
        vs[sl][j][d] = r[1024 + d];
    }
    __syncthreads();

    for (int idx = d; idx < 289; idx += 64) {
        int i = idx / 17;
        int j = idx - i * 17;
        float s = 0.f;
#pragma unroll
        for (int dd = 0; dd < 64; dd++) s += qs[sl][i][dd] * ks[sl][j][dd];
        S[sl][i][j] = s * 0.125f;
    }
    __syncthreads();

    if (d < 17) {
        float mx = -1e30f;
#pragma unroll
        for (int j = 0; j < 17; j++) mx = fmaxf(mx, S[sl][d][j]);
        float sum = 0.f;
#pragma unroll
        for (int j = 0; j < 17; j++) {
            float e = expf(S[sl][d][j] - mx);
            S[sl][d][j] = e;
            sum += e;
        }
        float inv = 1.f / sum;
#pragma unroll
        for (int j = 0; j < 17; j++) S[sl][d][j] *= inv;
    }
    __syncthreads();

    if (d == 0) {
        const int trip[13][3] = {
            {0,1,2},{1,2,3},{0,4,5},{4,5,6},{0,7,8},{7,8,9},{8,9,10},
            {7,8,11},{8,11,12},{11,12,13},{7,8,14},{8,14,15},{14,15,16}};
#pragma unroll
        for (int tt = 0; tt < 13; tt++) {
            int jp = trip[tt][0], j = trip[tt][1], jc = trip[tt][2];
            float half = S[sl][j][jp] * 0.5f;
            S[sl][j][jc] += half;
            S[sl][jc][j] += half;
        }
    }
    __syncthreads();

#pragma unroll
    for (int i = 0; i < 17; i++) {
        float o = 0.f;
#pragma unroll
        for (int j = 0; j < 17; j++) o += S[sl][i][j] * vs[sl][j][d];
        size_t idx = ((size_t)(bn * 17 + i)) * 512 + h * 64 + d;
        __half hh = __float2half(o);
        oh[idx] = hh;
        ol[idx] = __float2half(o - __half2float(hh));
    }
}

// ---------------------------------------------------------------------------
// LayerNorm (no affine) over last dim 512
// ---------------------------------------------------------------------------
__global__ __launch_bounds__(128)
void ln_kernel(const float* __restrict__ Y, float* __restrict__ O) {
    const int row = blockIdx.x;
    const int t = threadIdx.x;
    const float4* yp = reinterpret_cast<const float4*>(Y + (size_t)row * 512);
    float4* op = reinterpret_cast<float4*>(O + (size_t)row * 512);

    float4 v = yp[t];
    float s = v.x + v.y + v.z + v.w;
    float q = v.x * v.x + v.y * v.y + v.z * v.z + v.w * v.w;
#pragma unroll
    for (int o = 16; o > 0; o >>= 1) {
        s += __shfl_xor_sync(0xffffffffu, s, o);
        q += __shfl_xor_sync(0xffffffffu, q, o);
    }
    __shared__ float ss[4], sq[4];
    int w = t >> 5;
    if ((t & 31) == 0) { ss[w] = s; sq[w] = q; }
    __syncthreads();
    s = ss[0] + ss[1] + ss[2] + ss[3];
    q = sq[0] + sq[1] + sq[2] + sq[3];

    const float inv512 = 1.f / 512.f;
    float mean = s * inv512;
    float var = q * inv512 - mean * mean;
    float r = rsqrtf(var + 1e-5f);

    float4 o4;
    o4.x = (v.x - mean) * r;
    o4.y = (v.y - mean) * r;
    o4.z = (v.z - mean) * r;
    o4.w = (v.w - mean) * r;
    op[t] = o4;
}

// ---------------------------------------------------------------------------
extern "C" void kernel_launch(void* const* d_in, const int* in_sizes, int n_in,
                              void* d_out, int out_size) {
    const float* x     = (const float*)d_in[0];
    const float* Wqkv  = (const float*)d_in[1];
    const float* bqkv  = (const float*)d_in[2];
    const float* Wproj = (const float*)d_in[3];
    const float* bproj = (const float*)d_in[4];
    float* out = (float*)d_out;

    float *qkv, *y;
    __half *xh, *xl, *ah, *al, *w1h, *w2h;
    cudaGetSymbolAddress((void**)&qkv, g_qkv);
    cudaGetSymbolAddress((void**)&y, g_y);
    cudaGetSymbolAddress((void**)&xh, g_xh);
    cudaGetSymbolAddress((void**)&xl, g_xl);
    cudaGetSymbolAddress((void**)&ah, g_ah);
    cudaGetSymbolAddress((void**)&al, g_al);
    cudaGetSymbolAddress((void**)&w1h, g_w1h);
    cudaGetSymbolAddress((void**)&w2h, g_w2h);

    cudaFuncSetAttribute(gemm_mma, cudaFuncAttributeMaxDynamicSharedMemorySize, GEMM_SMEM);

    // 1) splits
    const int n4 = MROWS * CC / 4;
    split_kernel<<<(n4 + 255) / 256, 256>>>(x, xh, xl, n4);
    wsplit_kernel<<<dim3(1536 / 32, 512 / 32), dim3(32, 8)>>>(Wqkv, w1h, 512, 1536);
    wsplit_kernel<<<dim3(512 / 32, 512 / 32), dim3(32, 8)>>>(Wproj, w2h, 512, 512);

    // 2) GEMM1: qkv = x @ Wqkv + bqkv
    gemm_mma<<<dim3(1536 / 256, (MROWS + 127) / 128), 512, GEMM_SMEM>>>(
        xh, xl, w1h, bqkv, nullptr, qkv, MROWS, 1536);

    // 3) attention (writes split output)
    attn_kernel<<<BNF * 4, 128>>>(qkv, ah, al);

    // 4) GEMM2: y = att @ Wproj + bproj + x
    gemm_mma<<<dim3(512 / 256, (MROWS + 127) / 128), 512, GEMM_SMEM>>>(
        ah, al, w2h, bproj, x, y, MROWS, 512);

    // 5) LayerNorm
    ln_kernel<<<MROWS, 128>>>(y, out);
}

// round 9
// speedup vs baseline: 4.1845x; 1.4125x over previous
#include <cuda_runtime.h>
#include <cuda_fp16.h>
#include <math.h>
#include <stdint.h>

// Problem constants
#define BB 16
#define NN 243
#define JJ 17
#define CC 512
#define HH 8
#define MROWS (BB * NN * JJ)      // 66096
#define BNF   (BB * NN)           // 3888
#define KDIM  512

// Scratch (device globals: allocation-free per harness rules)
__device__ float g_qkv[(size_t)MROWS * 1536];
__device__ float g_y[(size_t)MROWS * CC];
__device__ __half g_xh[(size_t)MROWS * CC];
__device__ __half g_ah[(size_t)MROWS * CC];
__device__ __half g_w1h[1536 * 512];   // Wqkv^T fp16, [N][K]
__device__ __half g_w2h[512 * 512];    // Wproj^T fp16

// ---------------------------------------------------------------------------
// PTX helpers
// ---------------------------------------------------------------------------
__device__ __forceinline__ uint32_t smem_u32(const void* p) {
    uint32_t a;
    asm("{ .reg .u64 t; cvta.to.shared.u64 t, %1; cvt.u32.u64 %0, t; }"
        : "=r"(a) : "l"(p));
    return a;
}

#define CP_ASYNC16(dst, src, sz) \
    asm volatile("cp.async.cg.shared.global [%0], [%1], 16, %2;\n" \
                 :: "r"((uint32_t)(dst)), "l"(src), "r"(sz))
#define CP_COMMIT() asm volatile("cp.async.commit_group;\n" ::: "memory")
#define CP_WAIT1()  asm volatile("cp.async.wait_group 1;\n" ::: "memory")

#define LDSM4(r0, r1, r2, r3, a) \
    asm volatile("ldmatrix.sync.aligned.m8n8.x4.shared.b16 {%0,%1,%2,%3}, [%4];" \
                 : "=r"(r0), "=r"(r1), "=r"(r2), "=r"(r3) : "r"(a))

__device__ __forceinline__ void mma16816(float* c, const uint32_t* a, const uint32_t* b) {
    asm volatile(
        "mma.sync.aligned.m16n8k16.row.col.f32.f16.f16.f32 "
        "{%0,%1,%2,%3}, {%4,%5,%6,%7}, {%8,%9}, {%0,%1,%2,%3};\n"
        : "+f"(c[0]), "+f"(c[1]), "+f"(c[2]), "+f"(c[3])
        : "r"(a[0]), "r"(a[1]), "r"(a[2]), "r"(a[3]), "r"(b[0]), "r"(b[1]));
}

// ---------------------------------------------------------------------------
// fp16 HMMA GEMM: C(MxN) = A(MxK) @ B^T(NxK) + bias (+resid), fp32 accumulate.
// BM=128, BN=256, BK=32, 512 threads (16 warps 4x4), warp tile 32x64.
// 3-stage cp.async pipeline; ldmatrix from 80B-padded rows (conflict-free).
// K = 512. M ragged (zero-filled loads, guarded stores). N % 256 == 0.
// ---------------------------------------------------------------------------
#define ROWB 80                        // padded row stride in bytes (40 fp16)
#define ST_AH 0
#define ST_BH (128 * ROWB)             // 10240
#define STAGE_BYTES (ST_BH + 256 * ROWB)   // 30720
#define NSTAGE 3
#define GEMM_SMEM (NSTAGE * STAGE_BYTES)   // 92160

__device__ __forceinline__ void load_tile(
    uint32_t stage,
    const __half* __restrict__ Ah, const __half* __restrict__ Bh,
    int bm, int bn, int M, int kt, int tid)
{
    const int k0 = kt * 32;
    // A: 128 rows x 4 16B-chunks (512 threads -> 1 pass)
    {
        int row = tid >> 2, c = tid & 3;
        uint32_t dof = row * ROWB + c * 16;
        size_t ga = (size_t)(bm + row) * KDIM + k0 + c * 8;
        int p = ((bm + row) < M) ? 16 : 0;
        CP_ASYNC16(stage + ST_AH + dof, Ah + ga, p);
    }
    // B: 256 rows x 4 16B-chunks (2 passes)
#pragma unroll
    for (int i = 0; i < 2; i++) {
        int q = i * 512 + tid;
        int row = q >> 2, c = q & 3;
        uint32_t dof = row * ROWB + c * 16;
        size_t gb = (size_t)(bn + row) * KDIM + k0 + c * 8;
        CP_ASYNC16(stage + ST_BH + dof, Bh + gb, 16);
    }
}

__global__ void __launch_bounds__(512, 1) gemm_mma(
    const __half* __restrict__ Ah, const __half* __restrict__ Bh,
    const float* __restrict__ bias, const float* __restrict__ resid,
    float* __restrict__ Cm, int M, int N)
{
    extern __shared__ char smem[];
    const uint32_t sb = smem_u32(smem);
    const int tid = threadIdx.x;
    const int w = tid >> 5, lane = tid & 31;
    const int wm = w & 3;                 // 4 warp-rows of 32
    const int wn = w >> 2;                // 4 warp-cols of 64
    const int bn = blockIdx.x << 8;       // BN=256
    const int bm = blockIdx.y << 7;       // BM=128

    float acc[2][8][4];
#pragma unroll
    for (int i = 0; i < 2; i++)
#pragma unroll
        for (int j = 0; j < 8; j++)
#pragma unroll
            for (int e = 0; e < 4; e++) acc[i][j][e] = 0.f;

    const int lrow = lane & 15;
    const int lkb = (lane >> 4) << 4;     // k8-half byte offset
    const uint32_t a_lane_off = (wm * 32 + lrow) * ROWB + lkb;
    const uint32_t b_lane_off = (wn * 64 + lrow) * ROWB + lkb;

    const int T = KDIM / 32;              // 16
    load_tile(sb, Ah, Bh, bm, bn, M, 0, tid);
    CP_COMMIT();
    load_tile(sb + STAGE_BYTES, Ah, Bh, bm, bn, M, 1, tid);
    CP_COMMIT();

    int sidx = 0;
    for (int kt = 0; kt < T; kt++) {
        CP_WAIT1();                        // stage kt resident
        __syncthreads();

        if (kt + 2 < T)
            load_tile(sb + ((sidx + 2 >= NSTAGE) ? sidx + 2 - NSTAGE : sidx + 2) * STAGE_BYTES,
                      Ah, Bh, bm, bn, M, kt + 2, tid);
        CP_COMMIT();

        const uint32_t stage = sb + sidx * STAGE_BYTES;
#pragma unroll
        for (int kc = 0; kc < 2; kc++) {
            const uint32_t kbo = kc * 32;  // 16 fp16 = 32B per k16-chunk
            uint32_t ah[2][4];
#pragma unroll
            for (int mi = 0; mi < 2; mi++) {
                uint32_t ad = stage + a_lane_off + mi * (16 * ROWB) + kbo;
                LDSM4(ah[mi][0], ah[mi][1], ah[mi][2], ah[mi][3], ad + ST_AH);
            }
#pragma unroll
            for (int h2 = 0; h2 < 2; h2++) {       // two halves of 32 n-cols
                uint32_t bh[4][2];
#pragma unroll
                for (int njj = 0; njj < 2; njj++) {
                    int nj = h2 * 2 + njj;         // n16 tile index (0..3)
                    uint32_t bd = stage + b_lane_off + nj * (16 * ROWB) + kbo;
                    uint32_t h0, h1, h2r, h3;
                    LDSM4(h0, h1, h2r, h3, bd + ST_BH);
                    bh[njj * 2 + 0][0] = h0; bh[njj * 2 + 0][1] = h2r;
                    bh[njj * 2 + 1][0] = h1; bh[njj * 2 + 1][1] = h3;
                }
#pragma unroll
                for (int mi = 0; mi < 2; mi++)
#pragma unroll
                    for (int nq = 0; nq < 4; nq++)
                        mma16816(acc[mi][h2 * 4 + nq], ah[mi], bh[nq]);
            }
        }
        sidx = (sidx + 1 >= NSTAGE) ? 0 : sidx + 1;
    }

    // Epilogue: thread g*4+t holds (m=g, n=2t) and (m=g+8, n=2t) per 16x8 tile
    const int g = lane >> 2, t = lane & 3;
#pragma unroll
    for (int mi = 0; mi < 2; mi++) {
#pragma unroll
        for (int ni = 0; ni < 8; ni++) {
            int col = bn + wn * 64 + ni * 8 + t * 2;
            float bb0 = bias[col], bb1 = bias[col + 1];
            int r0 = bm + wm * 32 + mi * 16 + g;
            if (r0 < M) {
                float2 o;
                o.x = acc[mi][ni][0] + bb0;
                o.y = acc[mi][ni][1] + bb1;
                if (resid) {
                    const float2 rr = *(const float2*)(resid + (size_t)r0 * N + col);
                    o.x += rr.x; o.y += rr.y;
                }
                *(float2*)(Cm + (size_t)r0 * N + col) = o;
            }
            int r1 = r0 + 8;
            if (r1 < M) {
                float2 o;
                o.x = acc[mi][ni][2] + bb0;
                o.y = acc[mi][ni][3] + bb1;
                if (resid) {
                    const float2 rr = *(const float2*)(resid + (size_t)r1 * N + col);
                    o.x += rr.x; o.y += rr.y;
                }
                *(float2*)(Cm + (size_t)r1 * N + col) = o;
            }
        }
    }
}

// ---------------------------------------------------------------------------
// Elementwise fp32 -> fp16 convert
// ---------------------------------------------------------------------------
__global__ void cvt_kernel(const float* __restrict__ src,
                           __half* __restrict__ dst, int n4) {
    int i = blockIdx.x * blockDim.x + threadIdx.x;
    if (i >= n4) return;
    float4 v = ((const float4*)src)[i];
    __half2* dp = (__half2*)dst;
    dp[2 * i]     = __halves2half2(__float2half(v.x), __float2half(v.y));
    dp[2 * i + 1] = __halves2half2(__float2half(v.z), __float2half(v.w));
}

// Transpose to fp16: W (KxN row-major) -> hiT (NxK row-major)
__global__ void wsplit_kernel(const float* __restrict__ W,
                              __half* __restrict__ hiT, int K, int N) {
    __shared__ float t[32][33];
    const int n0 = blockIdx.x * 32, k0 = blockIdx.y * 32;
    const int tx = threadIdx.x, ty = threadIdx.y;
    for (int r = ty; r < 32; r += 8)
        t[r][tx] = W[(size_t)(k0 + r) * N + n0 + tx];
    __syncthreads();
    for (int r = ty; r < 32; r += 8) {
        float v = t[tx][r];                       // (k0+tx, n0+r)
        hiT[(size_t)(n0 + r) * K + k0 + tx] = __float2half(v);
    }
}

// ---------------------------------------------------------------------------
// Attention: 2 heads per 128-thread block. Row stride padded to 65 floats
// (conflict-free column reads). Output fp16.
// ---------------------------------------------------------------------------
#define APAD 65
__global__ __launch_bounds__(128)
void attn_kernel(const float* __restrict__ qkv, __half* __restrict__ oh) {
    const int blk = blockIdx.x;           // 0 .. BNF*4-1
    const int bn = blk >> 2;
    const int h  = ((blk & 3) << 1) + (threadIdx.x >> 6);
    const int sl = threadIdx.x >> 6;      // slice 0/1
    const int d  = threadIdx.x & 63;

    __shared__ float qs[2][17][APAD];
    __shared__ float ks[2][17][APAD];
    __shared__ float vs[2][17][APAD];
    __shared__ float S[2][17][17];

    const float* base = qkv + (size_t)bn * 17 * 1536 + h * 64;
#pragma unroll
    for (int j = 0; j < 17; j++) {
        const float* r = base + (size_t)j * 1536;
        qs[sl][j][d] = r[d];
        ks[sl][j][d] = r[512 + d];
        vs[sl][j][d] = r[1024 + d];
    }
    __syncthreads();

    for (int idx = d; idx < 289; idx += 64) {
        int i = idx / 17;
        int j = idx - i * 17;
        float s = 0.f;
#pragma unroll
        for (int dd = 0; dd < 64; dd++) s += qs[sl][i][dd] * ks[sl][j][dd];
        S[sl][i][j] = s * 0.125f;
    }
    __syncthreads();

    if (d < 17) {
        float mx = -1e30f;
#pragma unroll
        for (int j = 0; j < 17; j++) mx = fmaxf(mx, S[sl][d][j]);
        float sum = 0.f;
#pragma unroll
        for (int j = 0; j < 17; j++) {
            float e = expf(S[sl][d][j] - mx);
            S[sl][d][j] = e;
            sum += e;
        }
        float inv = 1.f / sum;
#pragma unroll
        for (int j = 0; j < 17; j++) S[sl][d][j] *= inv;
    }
    __syncthreads();

    if (d == 0) {
        const int trip[13][3] = {
            {0,1,2},{1,2,3},{0,4,5},{4,5,6},{0,7,8},{7,8,9},{8,9,10},
            {7,8,11},{8,11,12},{11,12,13},{7,8,14},{8,14,15},{14,15,16}};
#pragma unroll
        for (int tt = 0; tt < 13; tt++) {
            int jp = trip[tt][0], j = trip[tt][1], jc = trip[tt][2];
            float half = S[sl][j][jp] * 0.5f;
            S[sl][j][jc] += half;
            S[sl][jc][j] += half;
        }
    }
    __syncthreads();

#pragma unroll
    for (int i = 0; i < 17; i++) {
        float o = 0.f;
#pragma unroll
        for (int j = 0; j < 17; j++) o += S[sl][i][j] * vs[sl][j][d];
        oh[((size_t)(bn * 17 + i)) * 512 + h * 64 + d] = __float2half(o);
    }
}

// ---------------------------------------------------------------------------
// LayerNorm (no affine) over last dim 512
// ---------------------------------------------------------------------------
__global__ __launch_bounds__(128)
void ln_kernel(const float* __restrict__ Y, float* __restrict__ O) {
    const int row = blockIdx.x;
    const int t = threadIdx.x;
    const float4* yp = reinterpret_cast<const float4*>(Y + (size_t)row * 512);
    float4* op = reinterpret_cast<float4*>(O + (size_t)row * 512);

    float4 v = yp[t];
    float s = v.x + v.y + v.z + v.w;
    float q = v.x * v.x + v.y * v.y + v.z * v.z + v.w * v.w;
#pragma unroll
    for (int o = 16; o > 0; o >>= 1) {
        s += __shfl_xor_sync(0xffffffffu, s, o);
        q += __shfl_xor_sync(0xffffffffu, q, o);
    }
    __shared__ float ss[4], sq[4];
    int w = t >> 5;
    if ((t & 31) == 0) { ss[w] = s; sq[w] = q; }
    __syncthreads();
    s = ss[0] + ss[1] + ss[2] + ss[3];
    q = sq[0] + sq[1] + sq[2] + sq[3];

    const float inv512 = 1.f / 512.f;
    float mean = s * inv512;
    float var = q * inv512 - mean * mean;
    float r = rsqrtf(var + 1e-5f);

    float4 o4;
    o4.x = (v.x - mean) * r;
    o4.y = (v.y - mean) * r;
    o4.z = (v.z - mean) * r;
    o4.w = (v.w - mean) * r;
    op[t] = o4;
}

// ---------------------------------------------------------------------------
extern "C" void kernel_launch(void* const* d_in, const int* in_sizes, int n_in,
                              void* d_out, int out_size) {
    const float* x     = (const float*)d_in[0];
    const float* Wqkv  = (const float*)d_in[1];
    const float* bqkv  = (const float*)d_in[2];
    const float* Wproj = (const float*)d_in[3];
    const float* bproj = (const float*)d_in[4];
    float* out = (float*)d_out;

    float *qkv, *y;
    __half *xh, *ah, *w1h, *w2h;
    cudaGetSymbolAddress((void**)&qkv, g_qkv);
    cudaGetSymbolAddress((void**)&y, g_y);
    cudaGetSymbolAddress((void**)&xh, g_xh);
    cudaGetSymbolAddress((void**)&ah, g_ah);
    cudaGetSymbolAddress((void**)&w1h, g_w1h);
    cudaGetSymbolAddress((void**)&w2h, g_w2h);

    cudaFuncSetAttribute(gemm_mma, cudaFuncAttributeMaxDynamicSharedMemorySize, GEMM_SMEM);

    // 1) converts
    const int n4 = MROWS * CC / 4;
    cvt_kernel<<<(n4 + 255) / 256, 256>>>(x, xh, n4);
    wsplit_kernel<<<dim3(1536 / 32, 512 / 32), dim3(32, 8)>>>(Wqkv, w1h, 512, 1536);
    wsplit_kernel<<<dim3(512 / 32, 512 / 32), dim3(32, 8)>>>(Wproj, w2h, 512, 512);

    // 2) GEMM1: qkv = x @ Wqkv + bqkv
    gemm_mma<<<dim3(1536 / 256, (MROWS + 127) / 128), 512, GEMM_SMEM>>>(
        xh, w1h, bqkv, nullptr, qkv, MROWS, 1536);

    // 3) attention
    attn_kernel<<<BNF * 4, 128>>>(qkv, ah);

    // 4) GEMM2: y = att @ Wproj + bproj + x
    gemm_mma<<<dim3(512 / 256, (MROWS + 127) / 128), 512, GEMM_SMEM>>>(
        ah, w2h, bproj, x, y, MROWS, 512);

    // 5) LayerNorm
    ln_kernel<<<MROWS, 128>>>(y, out);
}

// round 10
// speedup vs baseline: 5.0413x; 1.2048x over previous
#include <cuda_runtime.h>
#include <cuda_fp16.h>
#include <math.h>
#include <stdint.h>

// Problem constants
#define BB 16
#define NN 243
#define JJ 17
#define CC 512
#define HH 8
#define MROWS (BB * NN * JJ)      // 66096
#define BNF   (BB * NN)           // 3888
#define KDIM  512

// Scratch (device globals: allocation-free per harness rules)
__device__ float g_qkv[(size_t)MROWS * 1536];
__device__ float g_y[(size_t)MROWS * CC];
__device__ __half g_xh[(size_t)MROWS * CC];
__device__ __half g_ah[(size_t)MROWS * CC];
__device__ __half g_w1h[1536 * 512];   // Wqkv^T fp16, [N][K]
__device__ __half g_w2h[512 * 512];    // Wproj^T fp16

// ---------------------------------------------------------------------------
// PTX helpers
// ---------------------------------------------------------------------------
__device__ __forceinline__ uint32_t smem_u32(const void* p) {
    uint32_t a;
    asm("{ .reg .u64 t; cvta.to.shared.u64 t, %1; cvt.u32.u64 %0, t; }"
        : "=r"(a) : "l"(p));
    return a;
}

#define CP_ASYNC16(dst, src, sz) \
    asm volatile("cp.async.cg.shared.global [%0], [%1], 16, %2;\n" \
                 :: "r"((uint32_t)(dst)), "l"(src), "r"(sz))
#define CP_COMMIT() asm volatile("cp.async.commit_group;\n" ::: "memory")
#define CP_WAIT1()  asm volatile("cp.async.wait_group 1;\n" ::: "memory")

#define LDSM4(r0, r1, r2, r3, a) \
    asm volatile("ldmatrix.sync.aligned.m8n8.x4.shared.b16 {%0,%1,%2,%3}, [%4];" \
                 : "=r"(r0), "=r"(r1), "=r"(r2), "=r"(r3) : "r"(a))

__device__ __forceinline__ void mma16816(float* c, const uint32_t* a, const uint32_t* b) {
    asm volatile(
        "mma.sync.aligned.m16n8k16.row.col.f32.f16.f16.f32 "
        "{%0,%1,%2,%3}, {%4,%5,%6,%7}, {%8,%9}, {%0,%1,%2,%3};\n"
        : "+f"(c[0]), "+f"(c[1]), "+f"(c[2]), "+f"(c[3])
        : "r"(a[0]), "r"(a[1]), "r"(a[2]), "r"(a[3]), "r"(b[0]), "r"(b[1]));
}

// ---------------------------------------------------------------------------
// fp16 HMMA GEMM: C(MxN) = A(MxK) @ B^T(NxK) + bias (+resid), fp32 accumulate.
// BM=128, BN=128, BK=32, 256 threads (8 warps 2x4), warp tile 64x32.
// 2 CTAs/SM (launch_bounds) so barriers of one CTA hide behind the other.
// 3-stage cp.async pipeline; ldmatrix from 80B-padded rows (conflict-free).
// ---------------------------------------------------------------------------
#define ROWB 80                        // padded row stride in bytes (40 fp16)
#define ST_A 0
#define ST_B (128 * ROWB)              // 10240
#define STAGE_BYTES (ST_B + 128 * ROWB)    // 20480
#define NSTAGE 3
#define GEMM_SMEM (NSTAGE * STAGE_BYTES)   // 61440

__device__ __forceinline__ void load_tile(
    uint32_t stage,
    const __half* __restrict__ Ah, const __half* __restrict__ Bh,
    int bm, int bn, int M, int kt, int tid)
{
    const int k0 = kt * 32;
#pragma unroll
    for (int i = 0; i < 2; i++) {     // A: 128 rows x 4 16B-chunks
        int q = i * 256 + tid;
        int row = q >> 2, c = q & 3;
        uint32_t dof = row * ROWB + c * 16;
        size_t ga = (size_t)(bm + row) * KDIM + k0 + c * 8;
        int p = ((bm + row) < M) ? 16 : 0;
        CP_ASYNC16(stage + ST_A + dof, Ah + ga, p);
    }
#pragma unroll
    for (int i = 0; i < 2; i++) {     // B: 128 rows x 4 16B-chunks
        int q = i * 256 + tid;
        int row = q >> 2, c = q & 3;
        uint32_t dof = row * ROWB + c * 16;
        size_t gb = (size_t)(bn + row) * KDIM + k0 + c * 8;
        CP_ASYNC16(stage + ST_B + dof, Bh + gb, 16);
    }
}

__global__ void __launch_bounds__(256, 2) gemm_mma(
    const __half* __restrict__ Ah, const __half* __restrict__ Bh,
    const float* __restrict__ bias, const float* __restrict__ resid,
    float* __restrict__ Cm, int M, int N)
{
    extern __shared__ char smem[];
    const uint32_t sb = smem_u32(smem);
    const int tid = threadIdx.x;
    const int w = tid >> 5, lane = tid & 31;
    const int wm = w & 1;                 // 2 warp-rows of 64
    const int wn = w >> 1;                // 4 warp-cols of 32
    const int bn = blockIdx.x << 7;       // BN=128
    const int bm = blockIdx.y << 7;       // BM=128

    float acc[4][4][4];
#pragma unroll
    for (int i = 0; i < 4; i++)
#pragma unroll
        for (int j = 0; j < 4; j++)
#pragma unroll
            for (int e = 0; e < 4; e++) acc[i][j][e] = 0.f;

    const int lrow = lane & 15;
    const int lkb = (lane >> 4) << 4;     // k8-half byte offset
    const uint32_t a_lane_off = (wm * 64 + lrow) * ROWB + lkb;
    const uint32_t b_lane_off = (wn * 32 + lrow) * ROWB + lkb;

    const int T = KDIM / 32;              // 16
    load_tile(sb, Ah, Bh, bm, bn, M, 0, tid);
    CP_COMMIT();
    load_tile(sb + STAGE_BYTES, Ah, Bh, bm, bn, M, 1, tid);
    CP_COMMIT();

    int sidx = 0;
    for (int kt = 0; kt < T; kt++) {
        CP_WAIT1();                        // stage kt resident
        __syncthreads();

        if (kt + 2 < T)
            load_tile(sb + ((sidx + 2 >= NSTAGE) ? sidx + 2 - NSTAGE : sidx + 2) * STAGE_BYTES,
                      Ah, Bh, bm, bn, M, kt + 2, tid);
        CP_COMMIT();

        const uint32_t stage = sb + sidx * STAGE_BYTES;
#pragma unroll
        for (int kc = 0; kc < 2; kc++) {
            const uint32_t kbo = kc * 32;  // 16 fp16 = 32B per k16-chunk
            uint32_t ah[4][4], bh[4][2];
#pragma unroll
            for (int mi = 0; mi < 4; mi++) {
                uint32_t ad = stage + a_lane_off + mi * (16 * ROWB) + kbo;
                LDSM4(ah[mi][0], ah[mi][1], ah[mi][2], ah[mi][3], ad + ST_A);
            }
#pragma unroll
            for (int nj = 0; nj < 2; nj++) {      // 2 n16 tiles
                uint32_t bd = stage + b_lane_off + nj * (16 * ROWB) + kbo;
                uint32_t h0, h1, h2r, h3;
                LDSM4(h0, h1, h2r, h3, bd + ST_B);
                bh[nj * 2 + 0][0] = h0; bh[nj * 2 + 0][1] = h2r;
                bh[nj * 2 + 1][0] = h1; bh[nj * 2 + 1][1] = h3;
            }
#pragma unroll
            for (int mi = 0; mi < 4; mi++)
#pragma unroll
                for (int nq = 0; nq < 4; nq++)
                    mma16816(acc[mi][nq], ah[mi], bh[nq]);
        }
        sidx = (sidx + 1 >= NSTAGE) ? 0 : sidx + 1;
    }

    // Epilogue: thread g*4+t holds (m=g, n=2t) and (m=g+8, n=2t) per 16x8 tile
    const int g = lane >> 2, t = lane & 3;
#pragma unroll
    for (int mi = 0; mi < 4; mi++) {
#pragma unroll
        for (int ni = 0; ni < 4; ni++) {
            int col = bn + wn * 32 + ni * 8 + t * 2;
            float bb0 = bias[col], bb1 = bias[col + 1];
            int r0 = bm + wm * 64 + mi * 16 + g;
            if (r0 < M) {
                float2 o;
                o.x = acc[mi][ni][0] + bb0;
                o.y = acc[mi][ni][1] + bb1;
                if (resid) {
                    const float2 rr = *(const float2*)(resid + (size_t)r0 * N + col);
                    o.x += rr.x; o.y += rr.y;
                }
                *(float2*)(Cm + (size_t)r0 * N + col) = o;
            }
            int r1 = r0 + 8;
            if (r1 < M) {
                float2 o;
                o.x = acc[mi][ni][2] + bb0;
                o.y = acc[mi][ni][3] + bb1;
                if (resid) {
                    const float2 rr = *(const float2*)(resid + (size_t)r1 * N + col);
                    o.x += rr.x; o.y += rr.y;
                }
                *(float2*)(Cm + (size_t)r1 * N + col) = o;
            }
        }
    }
}

// ---------------------------------------------------------------------------
// Elementwise fp32 -> fp16 convert
// ---------------------------------------------------------------------------
__global__ void cvt_kernel(const float* __restrict__ src,
                           __half* __restrict__ dst, int n4) {
    int i = blockIdx.x * blockDim.x + threadIdx.x;
    if (i >= n4) return;
    float4 v = ((const float4*)src)[i];
    __half2* dp = (__half2*)dst;
    dp[2 * i]     = __halves2half2(__float2half(v.x), __float2half(v.y));
    dp[2 * i + 1] = __halves2half2(__float2half(v.z), __float2half(v.w));
}

// Transpose to fp16: W (KxN row-major) -> hiT (NxK row-major)
__global__ void wsplit_kernel(const float* __restrict__ W,
                              __half* __restrict__ hiT, int K, int N) {
    __shared__ float t[32][33];
    const int n0 = blockIdx.x * 32, k0 = blockIdx.y * 32;
    const int tx = threadIdx.x, ty = threadIdx.y;
    for (int r = ty; r < 32; r += 8)
        t[r][tx] = W[(size_t)(k0 + r) * N + n0 + tx];
    __syncthreads();
    for (int r = ty; r < 32; r += 8) {
        float v = t[tx][r];                       // (k0+tx, n0+r)
        hiT[(size_t)(n0 + r) * K + k0 + tx] = __float2half(v);
    }
}

// ---------------------------------------------------------------------------
// Attention: 2 heads per 128-thread block.
// Scores via 3x3 register tiles (rows padded to 18 with a zero row):
// 6 row-reads per 9 outputs -> ~2.7x less smem traffic than untiled.
// P@V caches v in registers and reads S rows via float4 broadcast.
// ---------------------------------------------------------------------------
#define APAD 68
__global__ __launch_bounds__(128)
void attn_kernel(const float* __restrict__ qkv, __half* __restrict__ oh) {
    const int blk = blockIdx.x;           // 0 .. BNF*4-1
    const int bn = blk >> 2;
    const int h  = ((blk & 3) << 1) + (threadIdx.x >> 6);
    const int sl = threadIdx.x >> 6;      // slice 0/1
    const int d  = threadIdx.x & 63;

    __shared__ float qs[2][18][APAD];
    __shared__ float ks[2][18][APAD];
    __shared__ float vs[2][17][APAD];
    __shared__ float S[2][17][20];        // 80B rows (float4-aligned)

    const float* base = qkv + (size_t)bn * 17 * 1536 + h * 64;
#pragma unroll
    for (int j = 0; j < 17; j++) {
        const float* r = base + (size_t)j * 1536;
        qs[sl][j][d] = r[d];
        ks[sl][j][d] = r[512 + d];
        vs[sl][j][d] = r[1024 + d];
    }
    qs[sl][17][d] = 0.f;                  // zero pad row
    ks[sl][17][d] = 0.f;
    __syncthreads();

    // Scores: 6x6 grid of 3x3 tiles over the padded 18x18 domain; threads 0..35
    if (d < 36) {
        const int i0 = (d / 6) * 3;
        const int j0 = (d % 6) * 3;
        float a[3][3];
#pragma unroll
        for (int r = 0; r < 3; r++)
#pragma unroll
            for (int s = 0; s < 3; s++) a[r][s] = 0.f;

#pragma unroll
        for (int c = 0; c < 8; c++) {     // 8 chunks of 8 along head dim
            float qv[3][8], kv[3][8];
#pragma unroll
            for (int r = 0; r < 3; r++) {
                *(float4*)&qv[r][0] = *(const float4*)&qs[sl][i0 + r][c * 8];
                *(float4*)&qv[r][4] = *(const float4*)&qs[sl][i0 + r][c * 8 + 4];
                *(float4*)&kv[r][0] = *(const float4*)&ks[sl][j0 + r][c * 8];
                *(float4*)&kv[r][4] = *(const float4*)&ks[sl][j0 + r][c * 8 + 4];
            }
#pragma unroll
            for (int r = 0; r < 3; r++)
#pragma unroll
                for (int s = 0; s < 3; s++)
#pragma unroll
                    for (int e = 0; e < 8; e++)
                        a[r][s] += qv[r][e] * kv[s][e];
        }
#pragma unroll
        for (int r = 0; r < 3; r++)
#pragma unroll
            for (int s = 0; s < 3; s++)
                if (i0 + r < 17 && j0 + s < 17)
                    S[sl][i0 + r][j0 + s] = a[r][s] * 0.125f;
    }
    __syncthreads();

    if (d < 17) {
        float mx = -1e30f;
#pragma unroll
        for (int j = 0; j < 17; j++) mx = fmaxf(mx, S[sl][d][j]);
        float sum = 0.f;
#pragma unroll
        for (int j = 0; j < 17; j++) {
            float e = expf(S[sl][d][j] - mx);
            S[sl][d][j] = e;
            sum += e;
        }
        float inv = 1.f / sum;
#pragma unroll
        for (int j = 0; j < 17; j++) S[sl][d][j] *= inv;
    }
    __syncthreads();

    if (d == 0) {
        const int trip[13][3] = {
            {0,1,2},{1,2,3},{0,4,5},{4,5,6},{0,7,8},{7,8,9},{8,9,10},
            {7,8,11},{8,11,12},{11,12,13},{7,8,14},{8,14,15},{14,15,16}};
#pragma unroll
        for (int tt = 0; tt < 13; tt++) {
            int jp = trip[tt][0], j = trip[tt][1], jc = trip[tt][2];
            float half = S[sl][j][jp] * 0.5f;
            S[sl][j][jc] += half;
            S[sl][jc][j] += half;
        }
    }
    __syncthreads();

    // P@V: v cached in registers; S rows via float4 broadcast
    float v[17];
#pragma unroll
    for (int j = 0; j < 17; j++) v[j] = vs[sl][j][d];
#pragma unroll
    for (int i = 0; i < 17; i++) {
        const float4 s0 = *(const float4*)&S[sl][i][0];
        const float4 s1 = *(const float4*)&S[sl][i][4];
        const float4 s2 = *(const float4*)&S[sl][i][8];
        const float4 s3 = *(const float4*)&S[sl][i][12];
        const float s16 = S[sl][i][16];
        float o = s0.x * v[0] + s0.y * v[1] + s0.z * v[2] + s0.w * v[3]
                + s1.x * v[4] + s1.y * v[5] + s1.z * v[6] + s1.w * v[7]
                + s2.x * v[8] + s2.y * v[9] + s2.z * v[10] + s2.w * v[11]
                + s3.x * v[12] + s3.y * v[13] + s3.z * v[14] + s3.w * v[15]
                + s16 * v[16];
        oh[((size_t)(bn * 17 + i)) * 512 + h * 64 + d] = __float2half(o);
    }
}

// ---------------------------------------------------------------------------
// LayerNorm (no affine) over last dim 512
// ---------------------------------------------------------------------------
__global__ __launch_bounds__(128)
void ln_kernel(const float* __restrict__ Y, float* __restrict__ O) {
    const int row = blockIdx.x;
    const int t = threadIdx.x;
    const float4* yp = reinterpret_cast<const float4*>(Y + (size_t)row * 512);
    float4* op = reinterpret_cast<float4*>(O + (size_t)row * 512);

    float4 v = yp[t];
    float s = v.x + v.y + v.z + v.w;
    float q = v.x * v.x + v.y * v.y + v.z * v.z + v.w * v.w;
#pragma unroll
    for (int o = 16; o > 0; o >>= 1) {
        s += __shfl_xor_sync(0xffffffffu, s, o);
        q += __shfl_xor_sync(0xffffffffu, q, o);
    }
    __shared__ float ss[4], sq[4];
    int w = t >> 5;
    if ((t & 31) == 0) { ss[w] = s; sq[w] = q; }
    __syncthreads();
    s = ss[0] + ss[1] + ss[2] + ss[3];
    q = sq[0] + sq[1] + sq[2] + sq[3];

    const float inv512 = 1.f / 512.f;
    float mean = s * inv512;
    float var = q * inv512 - mean * mean;
    float r = rsqrtf(var + 1e-5f);

    float4 o4;
    o4.x = (v.x - mean) * r;
    o4.y = (v.y - mean) * r;
    o4.z = (v.z - mean) * r;
    o4.w = (v.w - mean) * r;
    op[t] = o4;
}

// ---------------------------------------------------------------------------
extern "C" void kernel_launch(void* const* d_in, const int* in_sizes, int n_in,
                              void* d_out, int out_size) {
    const float* x     = (const float*)d_in[0];
    const float* Wqkv  = (const float*)d_in[1];
    const float* bqkv  = (const float*)d_in[2];
    const float* Wproj = (const float*)d_in[3];
    const float* bproj = (const float*)d_in[4];
    float* out = (float*)d_out;

    float *qkv, *y;
    __half *xh, *ah, *w1h, *w2h;
    cudaGetSymbolAddress((void**)&qkv, g_qkv);
    cudaGetSymbolAddress((void**)&y, g_y);
    cudaGetSymbolAddress((void**)&xh, g_xh);
    cudaGetSymbolAddress((void**)&ah, g_ah);
    cudaGetSymbolAddress((void**)&w1h, g_w1h);
    cudaGetSymbolAddress((void**)&w2h, g_w2h);

    cudaFuncSetAttribute(gemm_mma, cudaFuncAttributeMaxDynamicSharedMemorySize, GEMM_SMEM);

    // 1) converts
    const int n4 = MROWS * CC / 4;
    cvt_kernel<<<(n4 + 255) / 256, 256>>>(x, xh, n4);
    wsplit_kernel<<<dim3(1536 / 32, 512 / 32), dim3(32, 8)>>>(Wqkv, w1h, 512, 1536);
    wsplit_kernel<<<dim3(512 / 32, 512 / 32), dim3(32, 8)>>>(Wproj, w2h, 512, 512);

    // 2) GEMM1: qkv = x @ Wqkv + bqkv
    gemm_mma<<<dim3(1536 / 128, (MROWS + 127) / 128), 256, GEMM_SMEM>>>(
        xh, w1h, bqkv, nullptr, qkv, MROWS, 1536);

    // 3) attention
    attn_kernel<<<BNF * 4, 128>>>(qkv, ah);

    // 4) GEMM2: y = att @ Wproj + bproj + x
    gemm_mma<<<dim3(512 / 128, (MROWS + 127) / 128), 256, GEMM_SMEM>>>(
        ah, w2h, bproj, x, y, MROWS, 512);

    // 5) LayerNorm
    ln_kernel<<<MROWS, 128>>>(y, out);
}